// round 12
// baseline (speedup 1.0000x reference)
#include <cuda_runtime.h>
#include <cuda_bf16.h>
#include <math.h>
#include <stdint.h>

#define BB 2
#define XL 256
#define CL 767
#define YL 768
#define SS 1024
#define DD 1024
#define FFD 4096
#define NLAYER 6
#define NH 16
#define DH 64
#define CVOC 1025
#define NPAD 1152
#define EOS_ID 1024
#define BOS_ID 1025
#define MROWS (BB*SS)
#define PROWS (BB*YL)

// ---------------- scratch (static device globals; no allocs) ----------------
__device__ float g_h[MROWS*DD];
__device__ __nv_bfloat16 g_hb[MROWS*DD];
__device__ __nv_bfloat16 g_qkvb[MROWS*3*DD];
__device__ __nv_bfloat16 g_attnb[MROWS*DD];
__device__ float g_tmp[MROWS*DD];
__device__ __nv_bfloat16 g_ffb[MROWS*FFD];
__device__ __nv_bfloat16 g_xb[PROWS*DD];
__device__ float g_logits[PROWS*NPAD];
__device__ float g_nll[PROWS];
// bf16 K-major weights [K,N] (no transpose)
__device__ __nv_bfloat16 g_Wqkv[NLAYER*DD*3*DD];
__device__ __nv_bfloat16 g_Wo[NLAYER*DD*DD];
__device__ __nv_bfloat16 g_W1[NLAYER*DD*FFD];
__device__ __nv_bfloat16 g_W2[NLAYER*FFD*DD];
__device__ __nv_bfloat16 g_proj[DD*NPAD];

// ---------------- helpers ----------------
__device__ __forceinline__ uint32_t smem_u32(const void* p) {
    uint32_t a;
    asm("{ .reg .u64 t; cvta.to.shared.u64 t, %1; cvt.u32.u64 %0, t; }" : "=r"(a) : "l"(p));
    return a;
}
__device__ __forceinline__ void cp16(void* smem_dst, const void* gsrc) {
    uint32_t s = smem_u32(smem_dst);
    asm volatile("cp.async.cg.shared.global [%0], [%1], 16;" :: "r"(s), "l"(gsrc));
}
__device__ __forceinline__ void cp_commit() { asm volatile("cp.async.commit_group;" ::: "memory"); }
__device__ __forceinline__ void cp_wait0()  { asm volatile("cp.async.wait_group 0;" ::: "memory"); }
__device__ __forceinline__ void cp_wait1()  { asm volatile("cp.async.wait_group 1;" ::: "memory"); }

__device__ __forceinline__ void ldm_x4(uint32_t* r, uint32_t addr) {
    asm volatile("ldmatrix.sync.aligned.m8n8.x4.shared.b16 {%0,%1,%2,%3}, [%4];"
        : "=r"(r[0]), "=r"(r[1]), "=r"(r[2]), "=r"(r[3]) : "r"(addr));
}
__device__ __forceinline__ void ldm_x4_t(uint32_t* r, uint32_t addr) {
    asm volatile("ldmatrix.sync.aligned.m8n8.x4.trans.shared.b16 {%0,%1,%2,%3}, [%4];"
        : "=r"(r[0]), "=r"(r[1]), "=r"(r[2]), "=r"(r[3]) : "r"(addr));
}
__device__ __forceinline__ void mma16816(float* c, const uint32_t* a, const uint32_t* b) {
    asm volatile("mma.sync.aligned.m16n8k16.row.col.f32.bf16.bf16.f32 "
        "{%0,%1,%2,%3}, {%4,%5,%6,%7}, {%8,%9}, {%0,%1,%2,%3};"
        : "+f"(c[0]), "+f"(c[1]), "+f"(c[2]), "+f"(c[3])
        : "r"(a[0]), "r"(a[1]), "r"(a[2]), "r"(a[3]), "r"(b[0]), "r"(b[1]));
}
__device__ __forceinline__ uint32_t pk(float x, float y) {
    __nv_bfloat162 p = __floats2bfloat162_rn(x, y);
    return *(uint32_t*)&p;
}

#define KCH 64
#define PADW 72                    // A-tile row pad (bf16 elems)
#define PADB 136                   // B-tile row pad (272B: conflict-free trans ldm)
#define PADB2 264                  // wide B-tile row pad (528B: conflict-free trans ldm)
#define ATILE_E (128*PADW)
#define BTILE_E (64*PADB)
#define BTILE2_E (64*PADB2)
#define NSTAGE 3
#define GEMM_SMEM (NSTAGE*(ATILE_E + BTILE_E)*2 + 512)
#define GEMM256_SMEM (NSTAGE*(ATILE_E + BTILE2_E)*2 + 1536)

// ---------------- HMMA bf16 GEMM (128x128 tile): C = A @ W (+bias)(+relu) ----------------
template<int OUT_BF16, int RELU, int HAS_BIAS>
__global__ void __launch_bounds__(256, 2) gemm_mma(void* __restrict__ Cv,
        const __nv_bfloat16* __restrict__ A, const __nv_bfloat16* __restrict__ W,
        const float* __restrict__ bias, int M, int K, int N) {
    extern __shared__ __nv_bfloat16 sm[];
    __nv_bfloat16* As = sm;
    __nv_bfloat16* Bs = sm + NSTAGE * ATILE_E;
    float* biasSm = (float*)(sm + NSTAGE * (ATILE_E + BTILE_E));

    int tid = threadIdx.x;
    int wid = tid >> 5, lane = tid & 31;
    int wm = wid >> 2, wn = wid & 3;
    int m0 = blockIdx.y * 128, n0 = blockIdx.x * 128;

    if (HAS_BIAS && tid < 128) biasSm[tid] = bias[n0 + tid];

    const __nv_bfloat16* gA = A + (size_t)m0 * K;
    const __nv_bfloat16* gB = W + n0;

    float acc[4][4][4];
#pragma unroll
    for (int i = 0; i < 4; i++)
#pragma unroll
        for (int j = 0; j < 4; j++)
#pragma unroll
            for (int q = 0; q < 4; q++) acc[i][j][q] = 0.f;

    const int nch = K / KCH;
    int ar = tid >> 3, ap = (tid & 7) * 8;
    int br = tid >> 4, bp = (tid & 15) * 8;

#pragma unroll
    for (int pc = 0; pc < 2; pc++) {
        __nv_bfloat16* dA = As + pc * ATILE_E;
        __nv_bfloat16* dB = Bs + pc * BTILE_E;
        const __nv_bfloat16* sA = gA + pc * KCH;
        const __nv_bfloat16* sB = gB + (size_t)pc * KCH * N;
#pragma unroll
        for (int i = 0; i < 4; i++) {
            cp16(dA + (ar + 32 * i) * PADW + ap, sA + (size_t)(ar + 32 * i) * K + ap);
            cp16(dB + (br + 16 * i) * PADB + bp, sB + (size_t)(br + 16 * i) * N + bp);
        }
        cp_commit();
    }

    int a_r = (lane & 7) + ((lane >> 3) & 1) * 8;
    int a_ch = (lane >> 4) * 8;

    for (int ic = 0; ic < nch; ic++) {
        if (ic + 1 < nch) cp_wait1(); else cp_wait0();
        __syncthreads();
        if (ic + 2 < nch) {
            int st = (ic + 2) % NSTAGE;
            __nv_bfloat16* dA = As + st * ATILE_E;
            __nv_bfloat16* dB = Bs + st * BTILE_E;
            const __nv_bfloat16* sA = gA + (size_t)(ic + 2) * KCH;
            const __nv_bfloat16* sB = gB + (size_t)(ic + 2) * KCH * N;
#pragma unroll
            for (int i = 0; i < 4; i++) {
                cp16(dA + (ar + 32 * i) * PADW + ap, sA + (size_t)(ar + 32 * i) * K + ap);
                cp16(dB + (br + 16 * i) * PADB + bp, sB + (size_t)(br + 16 * i) * N + bp);
            }
            cp_commit();
        }

        int cs = ic % NSTAGE;
        const __nv_bfloat16* As_ = As + cs * ATILE_E;
        const __nv_bfloat16* Bs_ = Bs + cs * BTILE_E;
#pragma unroll
        for (int ks = 0; ks < 4; ks++) {
            uint32_t a[4][4], b[2][4];
#pragma unroll
            for (int mi = 0; mi < 4; mi++)
                ldm_x4(a[mi], smem_u32(As_ + (size_t)(wm * 64 + mi * 16 + a_r) * PADW + ks * 16 + a_ch));
#pragma unroll
            for (int ni2 = 0; ni2 < 2; ni2++)
                ldm_x4_t(b[ni2], smem_u32(Bs_ + (size_t)(ks * 16 + (lane & 15)) * PADB + wn * 32 + ni2 * 16 + (lane >> 4) * 8));
#pragma unroll
            for (int mi = 0; mi < 4; mi++)
#pragma unroll
                for (int ni = 0; ni < 4; ni++)
                    mma16816(acc[mi][ni], a[mi], b[ni >> 1] + (ni & 1) * 2);
        }
    }

    int rg = lane >> 2, cg = (lane & 3) * 2;
#pragma unroll
    for (int mi = 0; mi < 4; mi++) {
#pragma unroll
        for (int ni = 0; ni < 4; ni++) {
            int colL = wn * 32 + ni * 8 + cg;
            int col = n0 + colL;
            float b0 = HAS_BIAS ? biasSm[colL] : 0.f;
            float b1 = HAS_BIAS ? biasSm[colL + 1] : 0.f;
#pragma unroll
            for (int rh = 0; rh < 2; rh++) {
                int row = m0 + wm * 64 + mi * 16 + rg + rh * 8;
                float v0 = acc[mi][ni][rh * 2 + 0] + b0;
                float v1 = acc[mi][ni][rh * 2 + 1] + b1;
                if (RELU) { v0 = fmaxf(v0, 0.f); v1 = fmaxf(v1, 0.f); }
                if (OUT_BF16) {
                    __nv_bfloat162 p = __floats2bfloat162_rn(v0, v1);
                    *(__nv_bfloat162*)((__nv_bfloat16*)Cv + (size_t)row * N + col) = p;
                } else {
                    *(float2*)((float*)Cv + (size_t)row * N + col) = make_float2(v0, v1);
                }
            }
        }
    }
}

// ---------------- HMMA bf16 GEMM (128x256 tile, warp tile 64x64, 1 CTA/SM) ----------------
template<int RELU>
__global__ void __launch_bounds__(256, 1) gemm_mma256(__nv_bfloat16* __restrict__ Cv,
        const __nv_bfloat16* __restrict__ A, const __nv_bfloat16* __restrict__ W,
        const float* __restrict__ bias, int M, int K, int N) {
    extern __shared__ __nv_bfloat16 sm[];
    __nv_bfloat16* As = sm;                          // [NSTAGE][128][PADW]
    __nv_bfloat16* Bs = sm + NSTAGE * ATILE_E;       // [NSTAGE][64][PADB2]
    float* biasSm = (float*)(sm + NSTAGE * (ATILE_E + BTILE2_E));

    int tid = threadIdx.x;
    int wid = tid >> 5, lane = tid & 31;
    int wm = wid >> 2, wn = wid & 3;                 // 2 x 4 warps, warp tile 64x64
    int m0 = blockIdx.y * 128, n0 = blockIdx.x * 256;

    biasSm[tid] = bias[n0 + tid];

    const __nv_bfloat16* gA = A + (size_t)m0 * K;
    const __nv_bfloat16* gB = W + n0;

    float acc[4][8][4];
#pragma unroll
    for (int i = 0; i < 4; i++)
#pragma unroll
        for (int j = 0; j < 8; j++)
#pragma unroll
            for (int q = 0; q < 4; q++) acc[i][j][q] = 0.f;

    const int nch = K / KCH;
    int ar = tid >> 3, ap = (tid & 7) * 8;

#pragma unroll
    for (int pc = 0; pc < 2; pc++) {
        __nv_bfloat16* dA = As + pc * ATILE_E;
        __nv_bfloat16* dB = Bs + pc * BTILE2_E;
        const __nv_bfloat16* sA = gA + pc * KCH;
        const __nv_bfloat16* sB = gB + (size_t)pc * KCH * N;
#pragma unroll
        for (int i = 0; i < 4; i++)
            cp16(dA + (ar + 32 * i) * PADW + ap, sA + (size_t)(ar + 32 * i) * K + ap);
#pragma unroll
        for (int i = 0; i < 8; i++) {
            int idx = tid + 256 * i;
            int brow = idx >> 5, bcol = (idx & 31) * 8;
            cp16(dB + brow * PADB2 + bcol, sB + (size_t)brow * N + bcol);
        }
        cp_commit();
    }

    int a_r = (lane & 7) + ((lane >> 3) & 1) * 8;
    int a_ch = (lane >> 4) * 8;

    for (int ic = 0; ic < nch; ic++) {
        if (ic + 1 < nch) cp_wait1(); else cp_wait0();
        __syncthreads();
        if (ic + 2 < nch) {
            int st = (ic + 2) % NSTAGE;
            __nv_bfloat16* dA = As + st * ATILE_E;
            __nv_bfloat16* dB = Bs + st * BTILE2_E;
            const __nv_bfloat16* sA = gA + (size_t)(ic + 2) * KCH;
            const __nv_bfloat16* sB = gB + (size_t)(ic + 2) * KCH * N;
#pragma unroll
            for (int i = 0; i < 4; i++)
                cp16(dA + (ar + 32 * i) * PADW + ap, sA + (size_t)(ar + 32 * i) * K + ap);
#pragma unroll
            for (int i = 0; i < 8; i++) {
                int idx = tid + 256 * i;
                int brow = idx >> 5, bcol = (idx & 31) * 8;
                cp16(dB + brow * PADB2 + bcol, sB + (size_t)brow * N + bcol);
            }
            cp_commit();
        }

        int cs = ic % NSTAGE;
        const __nv_bfloat16* As_ = As + cs * ATILE_E;
        const __nv_bfloat16* Bs_ = Bs + cs * BTILE2_E;
#pragma unroll
        for (int ks = 0; ks < 4; ks++) {
            uint32_t a[4][4], b[4][4];
#pragma unroll
            for (int mi = 0; mi < 4; mi++)
                ldm_x4(a[mi], smem_u32(As_ + (size_t)(wm * 64 + mi * 16 + a_r) * PADW + ks * 16 + a_ch));
#pragma unroll
            for (int nj = 0; nj < 4; nj++)
                ldm_x4_t(b[nj], smem_u32(Bs_ + (size_t)(ks * 16 + (lane & 15)) * PADB2 + wn * 64 + nj * 16 + (lane >> 4) * 8));
#pragma unroll
            for (int mi = 0; mi < 4; mi++)
#pragma unroll
                for (int ni = 0; ni < 8; ni++)
                    mma16816(acc[mi][ni], a[mi], b[ni >> 1] + (ni & 1) * 2);
        }
    }

    int rg = lane >> 2, cg = (lane & 3) * 2;
#pragma unroll
    for (int mi = 0; mi < 4; mi++) {
#pragma unroll
        for (int ni = 0; ni < 8; ni++) {
            int colL = wn * 64 + ni * 8 + cg;
            int col = n0 + colL;
            float b0 = biasSm[colL];
            float b1 = biasSm[colL + 1];
#pragma unroll
            for (int rh = 0; rh < 2; rh++) {
                int row = m0 + wm * 64 + mi * 16 + rg + rh * 8;
                float v0 = acc[mi][ni][rh * 2 + 0] + b0;
                float v1 = acc[mi][ni][rh * 2 + 1] + b1;
                if (RELU) { v0 = fmaxf(v0, 0.f); v1 = fmaxf(v1, 0.f); }
                __nv_bfloat162 p = __floats2bfloat162_rn(v0, v1);
                *(__nv_bfloat162*)(Cv + (size_t)row * N + col) = p;
            }
        }
    }
}

// ---------------- fused flash attention ----------------
#define FLASH_SMEM ((128*PADW + 2*64*PADW + 2*64*PADW) * 2)
__global__ void __launch_bounds__(256, 2) flash_attn(const __nv_bfloat16* __restrict__ qkvb) {
    extern __shared__ __nv_bfloat16 fsm[];
    __nv_bfloat16* Qs = fsm;
    __nv_bfloat16* Ks = fsm + 128 * PADW;
    __nv_bfloat16* Vs = fsm + 128 * PADW + 2 * 64 * PADW;

    int bh = blockIdx.y;
    int b = bh / NH, h = bh % NH;
    int i0 = blockIdx.x * 128;
    int ntile = ((i0 < XL) ? XL : (i0 + 128)) / 64;

    int tid = threadIdx.x, w = tid >> 5, lane = tid & 31;
    const __nv_bfloat16* base = qkvb + (size_t)(b * SS) * 3 * DD + h * DH;

#pragma unroll
    for (int i = 0; i < 4; i++) {
        int c = tid + 256 * i;
        int row = c >> 3, cc = c & 7;
        cp16(Qs + row * PADW + cc * 8, base + (size_t)(i0 + row) * 3 * DD + cc * 8);
    }
#pragma unroll
    for (int i = 0; i < 2; i++) {
        int c = tid + 256 * i;
        int row = c >> 3, cc = c & 7;
        cp16(Ks + row * PADW + cc * 8, base + (size_t)row * 3 * DD + DD + cc * 8);
        cp16(Vs + row * PADW + cc * 8, base + (size_t)row * 3 * DD + 2 * DD + cc * 8);
    }
    cp_commit();

    float m0 = -1e30f, m1 = -1e30f, l0 = 0.f, l1 = 0.f;
    float o[8][4];
#pragma unroll
    for (int dt = 0; dt < 8; dt++)
#pragma unroll
        for (int q = 0; q < 4; q++) o[dt][q] = 0.f;

    int a_r = (lane & 7) + ((lane >> 3) & 1) * 8;
    int a_ch = (lane >> 4) * 8;
    int b_r = (lane & 7) + (lane >> 4) * 8;
    int b_ch = ((lane >> 3) & 1) * 8;
    int r0g = i0 + w * 16 + (lane >> 2);

    for (int t = 0; t < ntile; t++) {
        int buf = t & 1;
        if (t + 1 < ntile) {
            int j1 = (t + 1) * 64, nb = (t + 1) & 1;
#pragma unroll
            for (int i = 0; i < 2; i++) {
                int c = tid + 256 * i;
                int row = c >> 3, cc = c & 7;
                cp16(Ks + nb * 64 * PADW + row * PADW + cc * 8, base + (size_t)(j1 + row) * 3 * DD + DD + cc * 8);
                cp16(Vs + nb * 64 * PADW + row * PADW + cc * 8, base + (size_t)(j1 + row) * 3 * DD + 2 * DD + cc * 8);
            }
            cp_commit();
            cp_wait1();
        } else {
            cp_wait0();
        }
        __syncthreads();
        const __nv_bfloat16* K_ = Ks + buf * 64 * PADW;
        const __nv_bfloat16* V_ = Vs + buf * 64 * PADW;

        float s[8][4];
#pragma unroll
        for (int nt = 0; nt < 8; nt++)
#pragma unroll
            for (int q = 0; q < 4; q++) s[nt][q] = 0.f;
#pragma unroll
        for (int kd = 0; kd < 4; kd++) {
            uint32_t a[4];
            ldm_x4(a, smem_u32(Qs + (size_t)(w * 16 + a_r) * PADW + kd * 16 + a_ch));
            uint32_t bb[4][4];
#pragma unroll
            for (int nj = 0; nj < 4; nj++)
                ldm_x4(bb[nj], smem_u32(K_ + (size_t)(nj * 16 + b_r) * PADW + kd * 16 + b_ch));
#pragma unroll
            for (int nt = 0; nt < 8; nt++)
                mma16816(s[nt], a, bb[nt >> 1] + (nt & 1) * 2);
        }

        const float SC = 0.125f * 1.44269504f;
        int j0 = t * 64;
        if (i0 >= XL && j0 + 63 >= i0) {
#pragma unroll
            for (int nt = 0; nt < 8; nt++) {
                int j = j0 + nt * 8 + (lane & 3) * 2;
                s[nt][0] = (j     <= r0g)     ? s[nt][0] * SC : -1e30f;
                s[nt][1] = (j + 1 <= r0g)     ? s[nt][1] * SC : -1e30f;
                s[nt][2] = (j     <= r0g + 8) ? s[nt][2] * SC : -1e30f;
                s[nt][3] = (j + 1 <= r0g + 8) ? s[nt][3] * SC : -1e30f;
            }
        } else {
#pragma unroll
            for (int nt = 0; nt < 8; nt++)
#pragma unroll
                for (int q = 0; q < 4; q++) s[nt][q] *= SC;
        }

        float t0 = -1e30f, t1 = -1e30f;
#pragma unroll
        for (int nt = 0; nt < 8; nt++) {
            t0 = fmaxf(t0, fmaxf(s[nt][0], s[nt][1]));
            t1 = fmaxf(t1, fmaxf(s[nt][2], s[nt][3]));
        }
        t0 = fmaxf(t0, __shfl_xor_sync(0xffffffff, t0, 1));
        t0 = fmaxf(t0, __shfl_xor_sync(0xffffffff, t0, 2));
        t1 = fmaxf(t1, __shfl_xor_sync(0xffffffff, t1, 1));
        t1 = fmaxf(t1, __shfl_xor_sync(0xffffffff, t1, 2));
        float mn0 = fmaxf(m0, t0), mn1 = fmaxf(m1, t1);
        float al0 = exp2f(m0 - mn0), al1 = exp2f(m1 - mn1);
        m0 = mn0; m1 = mn1;
        float rs0 = 0.f, rs1 = 0.f;
#pragma unroll
        for (int nt = 0; nt < 8; nt++) {
            s[nt][0] = exp2f(s[nt][0] - m0); rs0 += s[nt][0];
            s[nt][1] = exp2f(s[nt][1] - m0); rs0 += s[nt][1];
            s[nt][2] = exp2f(s[nt][2] - m1); rs1 += s[nt][2];
            s[nt][3] = exp2f(s[nt][3] - m1); rs1 += s[nt][3];
        }
        rs0 += __shfl_xor_sync(0xffffffff, rs0, 1);
        rs0 += __shfl_xor_sync(0xffffffff, rs0, 2);
        rs1 += __shfl_xor_sync(0xffffffff, rs1, 1);
        rs1 += __shfl_xor_sync(0xffffffff, rs1, 2);
        l0 = l0 * al0 + rs0; l1 = l1 * al1 + rs1;
#pragma unroll
        for (int dt = 0; dt < 8; dt++) {
            o[dt][0] *= al0; o[dt][1] *= al0;
            o[dt][2] *= al1; o[dt][3] *= al1;
        }

        uint32_t pa[4][4];
#pragma unroll
        for (int kt = 0; kt < 4; kt++) {
            pa[kt][0] = pk(s[2 * kt][0], s[2 * kt][1]);
            pa[kt][1] = pk(s[2 * kt][2], s[2 * kt][3]);
            pa[kt][2] = pk(s[2 * kt + 1][0], s[2 * kt + 1][1]);
            pa[kt][3] = pk(s[2 * kt + 1][2], s[2 * kt + 1][3]);
        }

#pragma unroll
        for (int kt = 0; kt < 4; kt++) {
#pragma unroll
            for (int dv = 0; dv < 4; dv++) {
                uint32_t vb[4];
                ldm_x4_t(vb, smem_u32(V_ + (size_t)(kt * 16 + (lane & 15)) * PADW + dv * 16 + (lane >> 4) * 8));
                mma16816(o[dv * 2], pa[kt], vb);
                mma16816(o[dv * 2 + 1], pa[kt], vb + 2);
            }
        }
        __syncthreads();
    }

    float inv0 = 1.f / l0, inv1 = 1.f / l1;
#pragma unroll
    for (int dt = 0; dt < 8; dt++) {
        int cols = h * DH + dt * 8 + (lane & 3) * 2;
        __nv_bfloat162 p0 = __floats2bfloat162_rn(o[dt][0] * inv0, o[dt][1] * inv0);
        __nv_bfloat162 p1 = __floats2bfloat162_rn(o[dt][2] * inv1, o[dt][3] * inv1);
        *(__nv_bfloat162*)(g_attnb + (size_t)(b * SS + r0g) * DD + cols) = p0;
        *(__nv_bfloat162*)(g_attnb + (size_t)(b * SS + r0g + 8) * DD + cols) = p1;
    }
}

// ---------------- streaming fp32 -> bf16 cast (all weights in one launch) ----------------
#define N4_QKV (NLAYER*DD*3*DD/4)
#define N4_WO  (NLAYER*DD*DD/4)
#define N4_W1  (NLAYER*DD*FFD/4)
#define N4_W2  (NLAYER*FFD*DD/4)
__global__ void wcast_all(const float* __restrict__ Wqkv, const float* __restrict__ Wo,
                          const float* __restrict__ W1, const float* __restrict__ W2) {
    const int total = N4_QKV + N4_WO + N4_W1 + N4_W2;
    int stride = gridDim.x * blockDim.x;
    for (int i = blockIdx.x * blockDim.x + threadIdx.x; i < total; i += stride) {
        const float4* src;
        uint2* dst;
        int j = i;
        if (j < N4_QKV) { src = (const float4*)Wqkv; dst = (uint2*)g_Wqkv; }
        else if ((j -= N4_QKV) < N4_WO) { src = (const float4*)Wo; dst = (uint2*)g_Wo; }
        else if ((j -= N4_WO) < N4_W1) { src = (const float4*)W1; dst = (uint2*)g_W1; }
        else { j -= N4_W1; src = (const float4*)W2; dst = (uint2*)g_W2; }
        float4 v = src[j];
        __nv_bfloat162 p0 = __floats2bfloat162_rn(v.x, v.y);
        __nv_bfloat162 p1 = __floats2bfloat162_rn(v.z, v.w);
        dst[j] = make_uint2(*(uint32_t*)&p0, *(uint32_t*)&p1);
    }
}
__global__ void projcast(const float* __restrict__ W, __nv_bfloat16* __restrict__ o) {
    int k = blockIdx.x;
    for (int n = threadIdx.x; n < NPAD; n += blockDim.x)
        o[(size_t)k * NPAD + n] = (n < CVOC) ? __float2bfloat16(W[(size_t)k * CVOC + n]) : __nv_bfloat16(0.f);
}

// ---------------- embedding + sinusoidal PE ----------------
__global__ void embed_kernel(const int* __restrict__ tokens, const int* __restrict__ codes,
                             const float* __restrict__ tok_emb, const float* __restrict__ audio_emb) {
    int row = blockIdx.x;
    int b = row / SS, s = row % SS;
    const float* src; int pos;
    if (s < XL) { src = tok_emb + (size_t)tokens[b*XL + s] * DD; pos = s; }
    else {
        int sy = s - XL;
        int id = (sy == 0) ? BOS_ID : codes[b*CL + sy - 1];
        src = audio_emb + (size_t)id * DD; pos = sy;
    }
    float* dst = g_h + (size_t)row * DD;
    __nv_bfloat16* dstb = g_hb + (size_t)row * DD;
    const float kinv = 9.210340371976184f / (float)DD;
    for (int d = threadIdx.x; d < DD; d += blockDim.x) {
        float freq = expf(-(float)(d & ~1) * kinv);
        float ang = (float)pos * freq;
        float pe = (d & 1) ? cosf(ang) : sinf(ang);
        float v = src[d] + pe;
        dst[d] = v;
        dstb[d] = __float2bfloat16(v);
    }
}

// ---------------- h = LN(h + p0); writes fp32 + bf16 ----------------
__global__ void __launch_bounds__(256) add_ln2(const float* __restrict__ p0,
        const float* __restrict__ w, const float* __restrict__ bvec) {
    __shared__ float red[8], red2[8];
    int row = blockIdx.x, tid = threadIdx.x, lane = tid & 31, wid = tid >> 5;

    float4 v = ((const float4*)(g_h + (size_t)row * DD))[tid];
    float4 q0 = ((const float4*)(p0 + (size_t)row * DD))[tid];
    v.x += q0.x; v.y += q0.y; v.z += q0.z; v.w += q0.w;

    float s = v.x + v.y + v.z + v.w;
#pragma unroll
    for (int o = 16; o; o >>= 1) s += __shfl_xor_sync(0xffffffff, s, o);
    if (lane == 0) red[wid] = s;
    __syncthreads();
    float tot = 0.f;
#pragma unroll
    for (int i = 0; i < 8; i++) tot += red[i];
    float mu = tot * (1.f / DD);

    float dx = v.x - mu, dy = v.y - mu, dz = v.z - mu, dw = v.w - mu;
    float s2 = dx * dx + dy * dy + dz * dz + dw * dw;
#pragma unroll
    for (int o = 16; o; o >>= 1) s2 += __shfl_xor_sync(0xffffffff, s2, o);
    if (lane == 0) red2[wid] = s2;
    __syncthreads();
    float tot2 = 0.f;
#pragma unroll
    for (int i = 0; i < 8; i++) tot2 += red2[i];
    float rstd = rsqrtf(tot2 * (1.f / DD) + 1e-5f);

    float4 w4 = ((const float4*)w)[tid];
    float4 b4 = ((const float4*)bvec)[tid];
    float4 out;
    out.x = dx * rstd * w4.x + b4.x;
    out.y = dy * rstd * w4.y + b4.y;
    out.z = dz * rstd * w4.z + b4.z;
    out.w = dw * rstd * w4.w + b4.w;
    ((float4*)(g_h + (size_t)row * DD))[tid] = out;
    __nv_bfloat162 h0 = __floats2bfloat162_rn(out.x, out.y);
    __nv_bfloat162 h1 = __floats2bfloat162_rn(out.z, out.w);
    ((uint2*)(g_hb + (size_t)row * DD))[tid] = make_uint2(*(uint32_t*)&h0, *(uint32_t*)&h1);
}

// ---------------- final LN on audio rows only -> bf16 gather ----------------
__global__ void __launch_bounds__(256) lnf_gather(const float* __restrict__ w,
                                                  const float* __restrict__ bvec) {
    __shared__ float red[8], red2[8];
    int m = blockIdx.x, tid = threadIdx.x, lane = tid & 31, wid = tid >> 5;
    int b = m / YL, t = m % YL;

    float4 v = ((const float4*)(g_h + (size_t)(b * SS + XL + t) * DD))[tid];
    float s = v.x + v.y + v.z + v.w;
#pragma unroll
    for (int o = 16; o; o >>= 1) s += __shfl_xor_sync(0xffffffff, s, o);
    if (lane == 0) red[wid] = s;
    __syncthreads();
    float tot = 0.f;
#pragma unroll
    for (int i = 0; i < 8; i++) tot += red[i];
    float mu = tot * (1.f / DD);

    float dx = v.x - mu, dy = v.y - mu, dz = v.z - mu, dw = v.w - mu;
    float s2 = dx * dx + dy * dy + dz * dz + dw * dw;
#pragma unroll
    for (int o = 16; o; o >>= 1) s2 += __shfl_xor_sync(0xffffffff, s2, o);
    if (lane == 0) red2[wid] = s2;
    __syncthreads();
    float tot2 = 0.f;
#pragma unroll
    for (int i = 0; i < 8; i++) tot2 += red2[i];
    float rstd = rsqrtf(tot2 * (1.f / DD) + 1e-5f);

    float4 w4 = ((const float4*)w)[tid];
    float4 b4 = ((const float4*)bvec)[tid];
    __nv_bfloat162 h0 = __floats2bfloat162_rn(dx * rstd * w4.x + b4.x, dy * rstd * w4.y + b4.y);
    __nv_bfloat162 h1 = __floats2bfloat162_rn(dz * rstd * w4.z + b4.z, dw * rstd * w4.w + b4.w);
    ((uint2*)(g_xb + (size_t)m * DD))[tid] = make_uint2(*(uint32_t*)&h0, *(uint32_t*)&h1);
}

// ---------------- per-row NLL ----------------
__device__ __forceinline__ float blk_reduce_max(float v, float* red) {
    int t = threadIdx.x;
    red[t] = v; __syncthreads();
    for (int s = 128; s > 0; s >>= 1) { if (t < s) red[t] = fmaxf(red[t], red[t + s]); __syncthreads(); }
    float r = red[0]; __syncthreads();
    return r;
}
__device__ __forceinline__ float blk_reduce_sum(float v, float* red) {
    int t = threadIdx.x;
    red[t] = v; __syncthreads();
    for (int s = 128; s > 0; s >>= 1) { if (t < s) red[t] += red[t + s]; __syncthreads(); }
    float r = red[0]; __syncthreads();
    return r;
}
__global__ void nll_kernel(const int* __restrict__ codes) {
    __shared__ float red[256];
    int m = blockIdx.x;
    int b = m / YL, t = m % YL;
    const float* row = g_logits + (size_t)m * NPAD;
    int tid = threadIdx.x;

    float lmax = -1e30f;
    for (int j = tid; j < CVOC; j += 256) lmax = fmaxf(lmax, row[j]);
    lmax = blk_reduce_max(lmax, red);
    float lsum = 0.f;
    for (int j = tid; j < CVOC; j += 256) lsum += expf(row[j] - lmax);
    lsum = blk_reduce_sum(lsum, red);
    if (tid == 0) {
        int tgt = (t < CL) ? codes[b * CL + t] : EOS_ID;
        g_nll[m] = lmax + logf(lsum) - row[tgt];
    }
}

__global__ void mean_kernel(float* __restrict__ out) {
    __shared__ float red[256];
    int tid = threadIdx.x;
    float s = 0.f;
    for (int i = tid; i < PROWS; i += 256) s += g_nll[i];
    s = blk_reduce_sum(s, red);
    if (tid == 0) out[0] = s / (float)PROWS;
}

// ---------------- launch ----------------
extern "C" void kernel_launch(void* const* d_in, const int* in_sizes, int n_in,
                              void* d_out, int out_size) {
    const int*   tokens    = (const int*)d_in[0];
    const int*   codes     = (const int*)d_in[1];
    const float* tok_emb   = (const float*)d_in[2];
    const float* audio_emb = (const float*)d_in[3];
    const float* Wqkv      = (const float*)d_in[4];
    const float* b_qkv     = (const float*)d_in[5];
    const float* Wo        = (const float*)d_in[6];
    const float* b_o       = (const float*)d_in[7];
    const float* W1        = (const float*)d_in[8];
    const float* b1        = (const float*)d_in[9];
    const float* W2        = (const float*)d_in[10];
    const float* b2        = (const float*)d_in[11];
    const float* ln1_w     = (const float*)d_in[12];
    const float* ln1_b     = (const float*)d_in[13];
    const float* ln2_w     = (const float*)d_in[14];
    const float* ln2_b     = (const float*)d_in[15];
    const float* lnf_w     = (const float*)d_in[16];
    const float* lnf_b     = (const float*)d_in[17];
    const float* proj_w    = (const float*)d_in[18];

    float *tmpP, *logitsP;
    __nv_bfloat16 *hbP, *qkvbP, *attnbP, *ffbP, *xbP, *WqkvP, *WoP, *W1P, *W2P, *projP;
    cudaGetSymbolAddress((void**)&hbP, g_hb);
    cudaGetSymbolAddress((void**)&qkvbP, g_qkvb);
    cudaGetSymbolAddress((void**)&attnbP, g_attnb);
    cudaGetSymbolAddress((void**)&tmpP, g_tmp);
    cudaGetSymbolAddress((void**)&ffbP, g_ffb);
    cudaGetSymbolAddress((void**)&xbP, g_xb);
    cudaGetSymbolAddress((void**)&logitsP, g_logits);
    cudaGetSymbolAddress((void**)&WqkvP, g_Wqkv);
    cudaGetSymbolAddress((void**)&WoP, g_Wo);
    cudaGetSymbolAddress((void**)&W1P, g_W1);
    cudaGetSymbolAddress((void**)&W2P, g_W2);
    cudaGetSymbolAddress((void**)&projP, g_proj);

    cudaFuncSetAttribute(gemm_mma<0,0,1>, cudaFuncAttributeMaxDynamicSharedMemorySize, GEMM_SMEM);
    cudaFuncSetAttribute(gemm_mma<0,0,0>, cudaFuncAttributeMaxDynamicSharedMemorySize, GEMM_SMEM);
    cudaFuncSetAttribute(gemm_mma256<0>, cudaFuncAttributeMaxDynamicSharedMemorySize, GEMM256_SMEM);
    cudaFuncSetAttribute(gemm_mma256<1>, cudaFuncAttributeMaxDynamicSharedMemorySize, GEMM256_SMEM);
    cudaFuncSetAttribute(flash_attn, cudaFuncAttributeMaxDynamicSharedMemorySize, FLASH_SMEM);

    wcast_all<<<2048, 256>>>(Wqkv, Wo, W1, W2);
    projcast<<<DD, 256>>>(proj_w, projP);

    embed_kernel<<<MROWS, 256>>>(tokens, codes, tok_emb, audio_emb);

    for (int l = 0; l < NLAYER; l++) {
        gemm_mma256<0><<<dim3(3*DD/256, MROWS/128), 256, GEMM256_SMEM>>>(
            qkvbP, hbP, WqkvP + (size_t)l*DD*3*DD, b_qkv + (size_t)l*3*DD, MROWS, DD, 3*DD);
        flash_attn<<<dim3(SS/128, BB*NH), 256, FLASH_SMEM>>>(qkvbP);
        gemm_mma<0,0,1><<<dim3(DD/128, MROWS/128), 256, GEMM_SMEM>>>(
            tmpP, attnbP, WoP + (size_t)l*DD*DD, b_o + (size_t)l*DD, MROWS, DD, DD);
        add_ln2<<<MROWS, 256>>>(tmpP, ln1_w + l*DD, ln1_b + l*DD);
        gemm_mma256<1><<<dim3(FFD/256, MROWS/128), 256, GEMM256_SMEM>>>(
            ffbP, hbP, W1P + (size_t)l*DD*FFD, b1 + (size_t)l*FFD, MROWS, DD, FFD);
        gemm_mma<0,0,1><<<dim3(DD/128, MROWS/128), 256, GEMM_SMEM>>>(
            tmpP, ffbP, W2P + (size_t)l*FFD*DD, b2 + (size_t)l*DD, MROWS, FFD, DD);
        add_ln2<<<MROWS, 256>>>(tmpP, ln2_w + l*DD, ln2_b + l*DD);
    }

    lnf_gather<<<PROWS, 256>>>(lnf_w, lnf_b);
    gemm_mma<0,0,0><<<dim3(NPAD/128, PROWS/128), 256, GEMM_SMEM>>>(
        logitsP, xbP, projP, nullptr, PROWS, DD, NPAD);
    nll_kernel<<<PROWS, 256>>>(codes);
    mean_kernel<<<1, 256>>>((float*)d_out);
}

// round 13
// speedup vs baseline: 1.0259x; 1.0259x over previous
#include <cuda_runtime.h>
#include <cuda_bf16.h>
#include <math.h>
#include <stdint.h>

#define BB 2
#define XL 256
#define CL 767
#define YL 768
#define SS 1024
#define DD 1024
#define FFD 4096
#define NLAYER 6
#define NH 16
#define DH 64
#define CVOC 1025
#define NPAD 1152
#define EOS_ID 1024
#define BOS_ID 1025
#define MROWS (BB*SS)
#define PROWS (BB*YL)

// ---------------- scratch (static device globals; no allocs) ----------------
__device__ float g_h[MROWS*DD];
__device__ __nv_bfloat16 g_hb[MROWS*DD];
__device__ __nv_bfloat16 g_qkvb[MROWS*3*DD];
__device__ __nv_bfloat16 g_attnb[MROWS*DD];
__device__ float g_tmp[MROWS*DD];
__device__ __nv_bfloat16 g_ffb[MROWS*FFD];
__device__ __nv_bfloat16 g_xb[PROWS*DD];
__device__ float g_logits[PROWS*NPAD];
__device__ float g_nll[PROWS];
// bf16 K-major weights [K,N] (no transpose)
__device__ __nv_bfloat16 g_Wqkv[NLAYER*DD*3*DD];
__device__ __nv_bfloat16 g_Wo[NLAYER*DD*DD];
__device__ __nv_bfloat16 g_W1[NLAYER*DD*FFD];
__device__ __nv_bfloat16 g_W2[NLAYER*FFD*DD];
__device__ __nv_bfloat16 g_proj[DD*NPAD];

// ---------------- helpers ----------------
__device__ __forceinline__ uint32_t smem_u32(const void* p) {
    uint32_t a;
    asm("{ .reg .u64 t; cvta.to.shared.u64 t, %1; cvt.u32.u64 %0, t; }" : "=r"(a) : "l"(p));
    return a;
}
__device__ __forceinline__ void cp16(void* smem_dst, const void* gsrc) {
    uint32_t s = smem_u32(smem_dst);
    asm volatile("cp.async.cg.shared.global [%0], [%1], 16;" :: "r"(s), "l"(gsrc));
}
__device__ __forceinline__ void cp_commit() { asm volatile("cp.async.commit_group;" ::: "memory"); }
__device__ __forceinline__ void cp_wait0()  { asm volatile("cp.async.wait_group 0;" ::: "memory"); }
__device__ __forceinline__ void cp_wait1()  { asm volatile("cp.async.wait_group 1;" ::: "memory"); }

__device__ __forceinline__ void ldm_x4(uint32_t* r, uint32_t addr) {
    asm volatile("ldmatrix.sync.aligned.m8n8.x4.shared.b16 {%0,%1,%2,%3}, [%4];"
        : "=r"(r[0]), "=r"(r[1]), "=r"(r[2]), "=r"(r[3]) : "r"(addr));
}
__device__ __forceinline__ void ldm_x4_t(uint32_t* r, uint32_t addr) {
    asm volatile("ldmatrix.sync.aligned.m8n8.x4.trans.shared.b16 {%0,%1,%2,%3}, [%4];"
        : "=r"(r[0]), "=r"(r[1]), "=r"(r[2]), "=r"(r[3]) : "r"(addr));
}
__device__ __forceinline__ void mma16816(float* c, const uint32_t* a, const uint32_t* b) {
    asm volatile("mma.sync.aligned.m16n8k16.row.col.f32.bf16.bf16.f32 "
        "{%0,%1,%2,%3}, {%4,%5,%6,%7}, {%8,%9}, {%0,%1,%2,%3};"
        : "+f"(c[0]), "+f"(c[1]), "+f"(c[2]), "+f"(c[3])
        : "r"(a[0]), "r"(a[1]), "r"(a[2]), "r"(a[3]), "r"(b[0]), "r"(b[1]));
}
__device__ __forceinline__ uint32_t pk(float x, float y) {
    __nv_bfloat162 p = __floats2bfloat162_rn(x, y);
    return *(uint32_t*)&p;
}

#define KCH 64
#define PADW 72                    // A-tile row pad (bf16 elems)
#define PADB 136                   // B-tile row pad (272B: conflict-free trans ldm)
#define ATILE_E (128*PADW)
#define ATILE64_E (64*PADW)
#define BTILE_E (64*PADB)
#define NSTAGE 3
#define GEMM_SMEM (NSTAGE*(ATILE_E + BTILE_E)*2 + 512)
#define GEMM64_SMEM (NSTAGE*(ATILE64_E + BTILE_E)*2 + 512)

// ---------------- HMMA bf16 GEMM (128x128 tile): C = A @ W (+bias)(+relu) ----------------
// grid (N/128, M/128), block 256 (8 warps: 2M x 4N; warp tile 64x32), 2 CTAs/SM, 3-stage
template<int OUT_BF16, int RELU, int HAS_BIAS>
__global__ void __launch_bounds__(256, 2) gemm_mma(void* __restrict__ Cv,
        const __nv_bfloat16* __restrict__ A, const __nv_bfloat16* __restrict__ W,
        const float* __restrict__ bias, int M, int K, int N) {
    extern __shared__ __nv_bfloat16 sm[];
    __nv_bfloat16* As = sm;
    __nv_bfloat16* Bs = sm + NSTAGE * ATILE_E;
    float* biasSm = (float*)(sm + NSTAGE * (ATILE_E + BTILE_E));

    int tid = threadIdx.x;
    int wid = tid >> 5, lane = tid & 31;
    int wm = wid >> 2, wn = wid & 3;
    int m0 = blockIdx.y * 128, n0 = blockIdx.x * 128;

    if (HAS_BIAS && tid < 128) biasSm[tid] = bias[n0 + tid];

    const __nv_bfloat16* gA = A + (size_t)m0 * K;
    const __nv_bfloat16* gB = W + n0;

    float acc[4][4][4];
#pragma unroll
    for (int i = 0; i < 4; i++)
#pragma unroll
        for (int j = 0; j < 4; j++)
#pragma unroll
            for (int q = 0; q < 4; q++) acc[i][j][q] = 0.f;

    const int nch = K / KCH;
    int ar = tid >> 3, ap = (tid & 7) * 8;
    int br = tid >> 4, bp = (tid & 15) * 8;

#pragma unroll
    for (int pc = 0; pc < 2; pc++) {
        __nv_bfloat16* dA = As + pc * ATILE_E;
        __nv_bfloat16* dB = Bs + pc * BTILE_E;
        const __nv_bfloat16* sA = gA + pc * KCH;
        const __nv_bfloat16* sB = gB + (size_t)pc * KCH * N;
#pragma unroll
        for (int i = 0; i < 4; i++) {
            cp16(dA + (ar + 32 * i) * PADW + ap, sA + (size_t)(ar + 32 * i) * K + ap);
            cp16(dB + (br + 16 * i) * PADB + bp, sB + (size_t)(br + 16 * i) * N + bp);
        }
        cp_commit();
    }

    int a_r = (lane & 7) + ((lane >> 3) & 1) * 8;
    int a_ch = (lane >> 4) * 8;

    for (int ic = 0; ic < nch; ic++) {
        if (ic + 1 < nch) cp_wait1(); else cp_wait0();
        __syncthreads();
        if (ic + 2 < nch) {
            int st = (ic + 2) % NSTAGE;
            __nv_bfloat16* dA = As + st * ATILE_E;
            __nv_bfloat16* dB = Bs + st * BTILE_E;
            const __nv_bfloat16* sA = gA + (size_t)(ic + 2) * KCH;
            const __nv_bfloat16* sB = gB + (size_t)(ic + 2) * KCH * N;
#pragma unroll
            for (int i = 0; i < 4; i++) {
                cp16(dA + (ar + 32 * i) * PADW + ap, sA + (size_t)(ar + 32 * i) * K + ap);
                cp16(dB + (br + 16 * i) * PADB + bp, sB + (size_t)(br + 16 * i) * N + bp);
            }
            cp_commit();
        }

        int cs = ic % NSTAGE;
        const __nv_bfloat16* As_ = As + cs * ATILE_E;
        const __nv_bfloat16* Bs_ = Bs + cs * BTILE_E;
#pragma unroll
        for (int ks = 0; ks < 4; ks++) {
            uint32_t a[4][4], b[2][4];
#pragma unroll
            for (int mi = 0; mi < 4; mi++)
                ldm_x4(a[mi], smem_u32(As_ + (size_t)(wm * 64 + mi * 16 + a_r) * PADW + ks * 16 + a_ch));
#pragma unroll
            for (int ni2 = 0; ni2 < 2; ni2++)
                ldm_x4_t(b[ni2], smem_u32(Bs_ + (size_t)(ks * 16 + (lane & 15)) * PADB + wn * 32 + ni2 * 16 + (lane >> 4) * 8));
#pragma unroll
            for (int mi = 0; mi < 4; mi++)
#pragma unroll
                for (int ni = 0; ni < 4; ni++)
                    mma16816(acc[mi][ni], a[mi], b[ni >> 1] + (ni & 1) * 2);
        }
    }

    int rg = lane >> 2, cg = (lane & 3) * 2;
#pragma unroll
    for (int mi = 0; mi < 4; mi++) {
#pragma unroll
        for (int ni = 0; ni < 4; ni++) {
            int colL = wn * 32 + ni * 8 + cg;
            int col = n0 + colL;
            float b0 = HAS_BIAS ? biasSm[colL] : 0.f;
            float b1 = HAS_BIAS ? biasSm[colL + 1] : 0.f;
#pragma unroll
            for (int rh = 0; rh < 2; rh++) {
                int row = m0 + wm * 64 + mi * 16 + rg + rh * 8;
                float v0 = acc[mi][ni][rh * 2 + 0] + b0;
                float v1 = acc[mi][ni][rh * 2 + 1] + b1;
                if (RELU) { v0 = fmaxf(v0, 0.f); v1 = fmaxf(v1, 0.f); }
                if (OUT_BF16) {
                    __nv_bfloat162 p = __floats2bfloat162_rn(v0, v1);
                    *(__nv_bfloat162*)((__nv_bfloat16*)Cv + (size_t)row * N + col) = p;
                } else {
                    *(float2*)((float*)Cv + (size_t)row * N + col) = make_float2(v0, v1);
                }
            }
        }
    }
}

// ---------------- HMMA bf16 GEMM (64x128 tile): for narrow-grid GEMMs (Wo/W2/proj) ----------------
// grid (N/128, M/64), block 256 (8 warps: 2M x 4N; warp tile 32x32), 2 CTAs/SM, 3-stage
template<int OUT_BF16, int HAS_BIAS>
__global__ void __launch_bounds__(256, 2) gemm_mma64(void* __restrict__ Cv,
        const __nv_bfloat16* __restrict__ A, const __nv_bfloat16* __restrict__ W,
        const float* __restrict__ bias, int M, int K, int N) {
    extern __shared__ __nv_bfloat16 sm[];
    __nv_bfloat16* As = sm;                          // [NSTAGE][64][PADW]
    __nv_bfloat16* Bs = sm + NSTAGE * ATILE64_E;     // [NSTAGE][64][PADB]
    float* biasSm = (float*)(sm + NSTAGE * (ATILE64_E + BTILE_E));

    int tid = threadIdx.x;
    int wid = tid >> 5, lane = tid & 31;
    int wm = wid >> 2, wn = wid & 3;                 // warp tile 32(M) x 32(N)
    int m0 = blockIdx.y * 64, n0 = blockIdx.x * 128;

    if (HAS_BIAS && tid < 128) biasSm[tid] = bias[n0 + tid];

    const __nv_bfloat16* gA = A + (size_t)m0 * K;
    const __nv_bfloat16* gB = W + n0;

    float acc[2][4][4];
#pragma unroll
    for (int i = 0; i < 2; i++)
#pragma unroll
        for (int j = 0; j < 4; j++)
#pragma unroll
            for (int q = 0; q < 4; q++) acc[i][j][q] = 0.f;

    const int nch = K / KCH;
    int ar = tid >> 3, ap = (tid & 7) * 8;           // A: 64 rows x 64, 2 cp16/thread
    int br = tid >> 4, bp = (tid & 15) * 8;          // B: 64 rows x 128, 4 cp16/thread

#pragma unroll
    for (int pc = 0; pc < 2; pc++) {
        __nv_bfloat16* dA = As + pc * ATILE64_E;
        __nv_bfloat16* dB = Bs + pc * BTILE_E;
        const __nv_bfloat16* sA = gA + pc * KCH;
        const __nv_bfloat16* sB = gB + (size_t)pc * KCH * N;
#pragma unroll
        for (int i = 0; i < 2; i++)
            cp16(dA + (ar + 32 * i) * PADW + ap, sA + (size_t)(ar + 32 * i) * K + ap);
#pragma unroll
        for (int i = 0; i < 4; i++)
            cp16(dB + (br + 16 * i) * PADB + bp, sB + (size_t)(br + 16 * i) * N + bp);
        cp_commit();
    }

    int a_r = (lane & 7) + ((lane >> 3) & 1) * 8;
    int a_ch = (lane >> 4) * 8;

    for (int ic = 0; ic < nch; ic++) {
        if (ic + 1 < nch) cp_wait1(); else cp_wait0();
        __syncthreads();
        if (ic + 2 < nch) {
            int st = (ic + 2) % NSTAGE;
            __nv_bfloat16* dA = As + st * ATILE64_E;
            __nv_bfloat16* dB = Bs + st * BTILE_E;
            const __nv_bfloat16* sA = gA + (size_t)(ic + 2) * KCH;
            const __nv_bfloat16* sB = gB + (size_t)(ic + 2) * KCH * N;
#pragma unroll
            for (int i = 0; i < 2; i++)
                cp16(dA + (ar + 32 * i) * PADW + ap, sA + (size_t)(ar + 32 * i) * K + ap);
#pragma unroll
            for (int i = 0; i < 4; i++)
                cp16(dB + (br + 16 * i) * PADB + bp, sB + (size_t)(br + 16 * i) * N + bp);
            cp_commit();
        }

        int cs = ic % NSTAGE;
        const __nv_bfloat16* As_ = As + cs * ATILE64_E;
        const __nv_bfloat16* Bs_ = Bs + cs * BTILE_E;
#pragma unroll
        for (int ks = 0; ks < 4; ks++) {
            uint32_t a[2][4], b[2][4];
#pragma unroll
            for (int mi = 0; mi < 2; mi++)
                ldm_x4(a[mi], smem_u32(As_ + (size_t)(wm * 32 + mi * 16 + a_r) * PADW + ks * 16 + a_ch));
#pragma unroll
            for (int ni2 = 0; ni2 < 2; ni2++)
                ldm_x4_t(b[ni2], smem_u32(Bs_ + (size_t)(ks * 16 + (lane & 15)) * PADB + wn * 32 + ni2 * 16 + (lane >> 4) * 8));
#pragma unroll
            for (int mi = 0; mi < 2; mi++)
#pragma unroll
                for (int ni = 0; ni < 4; ni++)
                    mma16816(acc[mi][ni], a[mi], b[ni >> 1] + (ni & 1) * 2);
        }
    }

    int rg = lane >> 2, cg = (lane & 3) * 2;
#pragma unroll
    for (int mi = 0; mi < 2; mi++) {
#pragma unroll
        for (int ni = 0; ni < 4; ni++) {
            int colL = wn * 32 + ni * 8 + cg;
            int col = n0 + colL;
            float b0 = HAS_BIAS ? biasSm[colL] : 0.f;
            float b1 = HAS_BIAS ? biasSm[colL + 1] : 0.f;
#pragma unroll
            for (int rh = 0; rh < 2; rh++) {
                int row = m0 + wm * 32 + mi * 16 + rg + rh * 8;
                float v0 = acc[mi][ni][rh * 2 + 0] + b0;
                float v1 = acc[mi][ni][rh * 2 + 1] + b1;
                if (OUT_BF16) {
                    __nv_bfloat162 p = __floats2bfloat162_rn(v0, v1);
                    *(__nv_bfloat162*)((__nv_bfloat16*)Cv + (size_t)row * N + col) = p;
                } else {
                    *(float2*)((float*)Cv + (size_t)row * N + col) = make_float2(v0, v1);
                }
            }
        }
    }
}

// ---------------- fused flash attention ----------------
#define FLASH_SMEM ((128*PADW + 2*64*PADW + 2*64*PADW) * 2)
__global__ void __launch_bounds__(256, 2) flash_attn(const __nv_bfloat16* __restrict__ qkvb) {
    extern __shared__ __nv_bfloat16 fsm[];
    __nv_bfloat16* Qs = fsm;
    __nv_bfloat16* Ks = fsm + 128 * PADW;
    __nv_bfloat16* Vs = fsm + 128 * PADW + 2 * 64 * PADW;

    int bh = blockIdx.y;
    int b = bh / NH, h = bh % NH;
    int i0 = blockIdx.x * 128;
    int ntile = ((i0 < XL) ? XL : (i0 + 128)) / 64;

    int tid = threadIdx.x, w = tid >> 5, lane = tid & 31;
    const __nv_bfloat16* base = qkvb + (size_t)(b * SS) * 3 * DD + h * DH;

#pragma unroll
    for (int i = 0; i < 4; i++) {
        int c = tid + 256 * i;
        int row = c >> 3, cc = c & 7;
        cp16(Qs + row * PADW + cc * 8, base + (size_t)(i0 + row) * 3 * DD + cc * 8);
    }
#pragma unroll
    for (int i = 0; i < 2; i++) {
        int c = tid + 256 * i;
        int row = c >> 3, cc = c & 7;
        cp16(Ks + row * PADW + cc * 8, base + (size_t)row * 3 * DD + DD + cc * 8);
        cp16(Vs + row * PADW + cc * 8, base + (size_t)row * 3 * DD + 2 * DD + cc * 8);
    }
    cp_commit();

    float m0 = -1e30f, m1 = -1e30f, l0 = 0.f, l1 = 0.f;
    float o[8][4];
#pragma unroll
    for (int dt = 0; dt < 8; dt++)
#pragma unroll
        for (int q = 0; q < 4; q++) o[dt][q] = 0.f;

    int a_r = (lane & 7) + ((lane >> 3) & 1) * 8;
    int a_ch = (lane >> 4) * 8;
    int b_r = (lane & 7) + (lane >> 4) * 8;
    int b_ch = ((lane >> 3) & 1) * 8;
    int r0g = i0 + w * 16 + (lane >> 2);

    for (int t = 0; t < ntile; t++) {
        int buf = t & 1;
        if (t + 1 < ntile) {
            int j1 = (t + 1) * 64, nb = (t + 1) & 1;
#pragma unroll
            for (int i = 0; i < 2; i++) {
                int c = tid + 256 * i;
                int row = c >> 3, cc = c & 7;
                cp16(Ks + nb * 64 * PADW + row * PADW + cc * 8, base + (size_t)(j1 + row) * 3 * DD + DD + cc * 8);
                cp16(Vs + nb * 64 * PADW + row * PADW + cc * 8, base + (size_t)(j1 + row) * 3 * DD + 2 * DD + cc * 8);
            }
            cp_commit();
            cp_wait1();
        } else {
            cp_wait0();
        }
        __syncthreads();
        const __nv_bfloat16* K_ = Ks + buf * 64 * PADW;
        const __nv_bfloat16* V_ = Vs + buf * 64 * PADW;

        float s[8][4];
#pragma unroll
        for (int nt = 0; nt < 8; nt++)
#pragma unroll
            for (int q = 0; q < 4; q++) s[nt][q] = 0.f;
#pragma unroll
        for (int kd = 0; kd < 4; kd++) {
            uint32_t a[4];
            ldm_x4(a, smem_u32(Qs + (size_t)(w * 16 + a_r) * PADW + kd * 16 + a_ch));
            uint32_t bb[4][4];
#pragma unroll
            for (int nj = 0; nj < 4; nj++)
                ldm_x4(bb[nj], smem_u32(K_ + (size_t)(nj * 16 + b_r) * PADW + kd * 16 + b_ch));
#pragma unroll
            for (int nt = 0; nt < 8; nt++)
                mma16816(s[nt], a, bb[nt >> 1] + (nt & 1) * 2);
        }

        const float SC = 0.125f * 1.44269504f;
        int j0 = t * 64;
        if (i0 >= XL && j0 + 63 >= i0) {
#pragma unroll
            for (int nt = 0; nt < 8; nt++) {
                int j = j0 + nt * 8 + (lane & 3) * 2;
                s[nt][0] = (j     <= r0g)     ? s[nt][0] * SC : -1e30f;
                s[nt][1] = (j + 1 <= r0g)     ? s[nt][1] * SC : -1e30f;
                s[nt][2] = (j     <= r0g + 8) ? s[nt][2] * SC : -1e30f;
                s[nt][3] = (j + 1 <= r0g + 8) ? s[nt][3] * SC : -1e30f;
            }
        } else {
#pragma unroll
            for (int nt = 0; nt < 8; nt++)
#pragma unroll
                for (int q = 0; q < 4; q++) s[nt][q] *= SC;
        }

        float t0 = -1e30f, t1 = -1e30f;
#pragma unroll
        for (int nt = 0; nt < 8; nt++) {
            t0 = fmaxf(t0, fmaxf(s[nt][0], s[nt][1]));
            t1 = fmaxf(t1, fmaxf(s[nt][2], s[nt][3]));
        }
        t0 = fmaxf(t0, __shfl_xor_sync(0xffffffff, t0, 1));
        t0 = fmaxf(t0, __shfl_xor_sync(0xffffffff, t0, 2));
        t1 = fmaxf(t1, __shfl_xor_sync(0xffffffff, t1, 1));
        t1 = fmaxf(t1, __shfl_xor_sync(0xffffffff, t1, 2));
        float mn0 = fmaxf(m0, t0), mn1 = fmaxf(m1, t1);
        float al0 = exp2f(m0 - mn0), al1 = exp2f(m1 - mn1);
        m0 = mn0; m1 = mn1;
        float rs0 = 0.f, rs1 = 0.f;
#pragma unroll
        for (int nt = 0; nt < 8; nt++) {
            s[nt][0] = exp2f(s[nt][0] - m0); rs0 += s[nt][0];
            s[nt][1] = exp2f(s[nt][1] - m0); rs0 += s[nt][1];
            s[nt][2] = exp2f(s[nt][2] - m1); rs1 += s[nt][2];
            s[nt][3] = exp2f(s[nt][3] - m1); rs1 += s[nt][3];
        }
        rs0 += __shfl_xor_sync(0xffffffff, rs0, 1);
        rs0 += __shfl_xor_sync(0xffffffff, rs0, 2);
        rs1 += __shfl_xor_sync(0xffffffff, rs1, 1);
        rs1 += __shfl_xor_sync(0xffffffff, rs1, 2);
        l0 = l0 * al0 + rs0; l1 = l1 * al1 + rs1;
#pragma unroll
        for (int dt = 0; dt < 8; dt++) {
            o[dt][0] *= al0; o[dt][1] *= al0;
            o[dt][2] *= al1; o[dt][3] *= al1;
        }

        uint32_t pa[4][4];
#pragma unroll
        for (int kt = 0; kt < 4; kt++) {
            pa[kt][0] = pk(s[2 * kt][0], s[2 * kt][1]);
            pa[kt][1] = pk(s[2 * kt][2], s[2 * kt][3]);
            pa[kt][2] = pk(s[2 * kt + 1][0], s[2 * kt + 1][1]);
            pa[kt][3] = pk(s[2 * kt + 1][2], s[2 * kt + 1][3]);
        }

#pragma unroll
        for (int kt = 0; kt < 4; kt++) {
#pragma unroll
            for (int dv = 0; dv < 4; dv++) {
                uint32_t vb[4];
                ldm_x4_t(vb, smem_u32(V_ + (size_t)(kt * 16 + (lane & 15)) * PADW + dv * 16 + (lane >> 4) * 8));
                mma16816(o[dv * 2], pa[kt], vb);
                mma16816(o[dv * 2 + 1], pa[kt], vb + 2);
            }
        }
        __syncthreads();
    }

    float inv0 = 1.f / l0, inv1 = 1.f / l1;
#pragma unroll
    for (int dt = 0; dt < 8; dt++) {
        int cols = h * DH + dt * 8 + (lane & 3) * 2;
        __nv_bfloat162 p0 = __floats2bfloat162_rn(o[dt][0] * inv0, o[dt][1] * inv0);
        __nv_bfloat162 p1 = __floats2bfloat162_rn(o[dt][2] * inv1, o[dt][3] * inv1);
        *(__nv_bfloat162*)(g_attnb + (size_t)(b * SS + r0g) * DD + cols) = p0;
        *(__nv_bfloat162*)(g_attnb + (size_t)(b * SS + r0g + 8) * DD + cols) = p1;
    }
}

// ---------------- streaming fp32 -> bf16 cast (all weights in one launch) ----------------
#define N4_QKV (NLAYER*DD*3*DD/4)
#define N4_WO  (NLAYER*DD*DD/4)
#define N4_W1  (NLAYER*DD*FFD/4)
#define N4_W2  (NLAYER*FFD*DD/4)
__global__ void wcast_all(const float* __restrict__ Wqkv, const float* __restrict__ Wo,
                          const float* __restrict__ W1, const float* __restrict__ W2) {
    const int total = N4_QKV + N4_WO + N4_W1 + N4_W2;
    int stride = gridDim.x * blockDim.x;
    for (int i = blockIdx.x * blockDim.x + threadIdx.x; i < total; i += stride) {
        const float4* src;
        uint2* dst;
        int j = i;
        if (j < N4_QKV) { src = (const float4*)Wqkv; dst = (uint2*)g_Wqkv; }
        else if ((j -= N4_QKV) < N4_WO) { src = (const float4*)Wo; dst = (uint2*)g_Wo; }
        else if ((j -= N4_WO) < N4_W1) { src = (const float4*)W1; dst = (uint2*)g_W1; }
        else { j -= N4_W1; src = (const float4*)W2; dst = (uint2*)g_W2; }
        float4 v = src[j];
        __nv_bfloat162 p0 = __floats2bfloat162_rn(v.x, v.y);
        __nv_bfloat162 p1 = __floats2bfloat162_rn(v.z, v.w);
        dst[j] = make_uint2(*(uint32_t*)&p0, *(uint32_t*)&p1);
    }
}
__global__ void projcast(const float* __restrict__ W, __nv_bfloat16* __restrict__ o) {
    int k = blockIdx.x;
    for (int n = threadIdx.x; n < NPAD; n += blockDim.x)
        o[(size_t)k * NPAD + n] = (n < CVOC) ? __float2bfloat16(W[(size_t)k * CVOC + n]) : __nv_bfloat16(0.f);
}

// ---------------- embedding + sinusoidal PE ----------------
__global__ void embed_kernel(const int* __restrict__ tokens, const int* __restrict__ codes,
                             const float* __restrict__ tok_emb, const float* __restrict__ audio_emb) {
    int row = blockIdx.x;
    int b = row / SS, s = row % SS;
    const float* src; int pos;
    if (s < XL) { src = tok_emb + (size_t)tokens[b*XL + s] * DD; pos = s; }
    else {
        int sy = s - XL;
        int id = (sy == 0) ? BOS_ID : codes[b*CL + sy - 1];
        src = audio_emb + (size_t)id * DD; pos = sy;
    }
    float* dst = g_h + (size_t)row * DD;
    __nv_bfloat16* dstb = g_hb + (size_t)row * DD;
    const float kinv = 9.210340371976184f / (float)DD;
    for (int d = threadIdx.x; d < DD; d += blockDim.x) {
        float freq = expf(-(float)(d & ~1) * kinv);
        float ang = (float)pos * freq;
        float pe = (d & 1) ? cosf(ang) : sinf(ang);
        float v = src[d] + pe;
        dst[d] = v;
        dstb[d] = __float2bfloat16(v);
    }
}

// ---------------- h = LN(h + p0); writes fp32 + bf16 ----------------
__global__ void __launch_bounds__(256) add_ln2(const float* __restrict__ p0,
        const float* __restrict__ w, const float* __restrict__ bvec) {
    __shared__ float red[8], red2[8];
    int row = blockIdx.x, tid = threadIdx.x, lane = tid & 31, wid = tid >> 5;

    float4 v = ((const float4*)(g_h + (size_t)row * DD))[tid];
    float4 q0 = ((const float4*)(p0 + (size_t)row * DD))[tid];
    v.x += q0.x; v.y += q0.y; v.z += q0.z; v.w += q0.w;

    float s = v.x + v.y + v.z + v.w;
#pragma unroll
    for (int o = 16; o; o >>= 1) s += __shfl_xor_sync(0xffffffff, s, o);
    if (lane == 0) red[wid] = s;
    __syncthreads();
    float tot = 0.f;
#pragma unroll
    for (int i = 0; i < 8; i++) tot += red[i];
    float mu = tot * (1.f / DD);

    float dx = v.x - mu, dy = v.y - mu, dz = v.z - mu, dw = v.w - mu;
    float s2 = dx * dx + dy * dy + dz * dz + dw * dw;
#pragma unroll
    for (int o = 16; o; o >>= 1) s2 += __shfl_xor_sync(0xffffffff, s2, o);
    if (lane == 0) red2[wid] = s2;
    __syncthreads();
    float tot2 = 0.f;
#pragma unroll
    for (int i = 0; i < 8; i++) tot2 += red2[i];
    float rstd = rsqrtf(tot2 * (1.f / DD) + 1e-5f);

    float4 w4 = ((const float4*)w)[tid];
    float4 b4 = ((const float4*)bvec)[tid];
    float4 out;
    out.x = dx * rstd * w4.x + b4.x;
    out.y = dy * rstd * w4.y + b4.y;
    out.z = dz * rstd * w4.z + b4.z;
    out.w = dw * rstd * w4.w + b4.w;
    ((float4*)(g_h + (size_t)row * DD))[tid] = out;
    __nv_bfloat162 h0 = __floats2bfloat162_rn(out.x, out.y);
    __nv_bfloat162 h1 = __floats2bfloat162_rn(out.z, out.w);
    ((uint2*)(g_hb + (size_t)row * DD))[tid] = make_uint2(*(uint32_t*)&h0, *(uint32_t*)&h1);
}

// ---------------- final LN on audio rows only -> bf16 gather ----------------
__global__ void __launch_bounds__(256) lnf_gather(const float* __restrict__ w,
                                                  const float* __restrict__ bvec) {
    __shared__ float red[8], red2[8];
    int m = blockIdx.x, tid = threadIdx.x, lane = tid & 31, wid = tid >> 5;
    int b = m / YL, t = m % YL;

    float4 v = ((const float4*)(g_h + (size_t)(b * SS + XL + t) * DD))[tid];
    float s = v.x + v.y + v.z + v.w;
#pragma unroll
    for (int o = 16; o; o >>= 1) s += __shfl_xor_sync(0xffffffff, s, o);
    if (lane == 0) red[wid] = s;
    __syncthreads();
    float tot = 0.f;
#pragma unroll
    for (int i = 0; i < 8; i++) tot += red[i];
    float mu = tot * (1.f / DD);

    float dx = v.x - mu, dy = v.y - mu, dz = v.z - mu, dw = v.w - mu;
    float s2 = dx * dx + dy * dy + dz * dz + dw * dw;
#pragma unroll
    for (int o = 16; o; o >>= 1) s2 += __shfl_xor_sync(0xffffffff, s2, o);
    if (lane == 0) red2[wid] = s2;
    __syncthreads();
    float tot2 = 0.f;
#pragma unroll
    for (int i = 0; i < 8; i++) tot2 += red2[i];
    float rstd = rsqrtf(tot2 * (1.f / DD) + 1e-5f);

    float4 w4 = ((const float4*)w)[tid];
    float4 b4 = ((const float4*)bvec)[tid];
    __nv_bfloat162 h0 = __floats2bfloat162_rn(dx * rstd * w4.x + b4.x, dy * rstd * w4.y + b4.y);
    __nv_bfloat162 h1 = __floats2bfloat162_rn(dz * rstd * w4.z + b4.z, dw * rstd * w4.w + b4.w);
    ((uint2*)(g_xb + (size_t)m * DD))[tid] = make_uint2(*(uint32_t*)&h0, *(uint32_t*)&h1);
}

// ---------------- per-row NLL ----------------
__device__ __forceinline__ float blk_reduce_max(float v, float* red) {
    int t = threadIdx.x;
    red[t] = v; __syncthreads();
    for (int s = 128; s > 0; s >>= 1) { if (t < s) red[t] = fmaxf(red[t], red[t + s]); __syncthreads(); }
    float r = red[0]; __syncthreads();
    return r;
}
__device__ __forceinline__ float blk_reduce_sum(float v, float* red) {
    int t = threadIdx.x;
    red[t] = v; __syncthreads();
    for (int s = 128; s > 0; s >>= 1) { if (t < s) red[t] += red[t + s]; __syncthreads(); }
    float r = red[0]; __syncthreads();
    return r;
}
__global__ void nll_kernel(const int* __restrict__ codes) {
    __shared__ float red[256];
    int m = blockIdx.x;
    int b = m / YL, t = m % YL;
    const float* row = g_logits + (size_t)m * NPAD;
    int tid = threadIdx.x;

    float lmax = -1e30f;
    for (int j = tid; j < CVOC; j += 256) lmax = fmaxf(lmax, row[j]);
    lmax = blk_reduce_max(lmax, red);
    float lsum = 0.f;
    for (int j = tid; j < CVOC; j += 256) lsum += expf(row[j] - lmax);
    lsum = blk_reduce_sum(lsum, red);
    if (tid == 0) {
        int tgt = (t < CL) ? codes[b * CL + t] : EOS_ID;
        g_nll[m] = lmax + logf(lsum) - row[tgt];
    }
}

__global__ void mean_kernel(float* __restrict__ out) {
    __shared__ float red[256];
    int tid = threadIdx.x;
    float s = 0.f;
    for (int i = tid; i < PROWS; i += 256) s += g_nll[i];
    s = blk_reduce_sum(s, red);
    if (tid == 0) out[0] = s / (float)PROWS;
}

// ---------------- launch ----------------
extern "C" void kernel_launch(void* const* d_in, const int* in_sizes, int n_in,
                              void* d_out, int out_size) {
    const int*   tokens    = (const int*)d_in[0];
    const int*   codes     = (const int*)d_in[1];
    const float* tok_emb   = (const float*)d_in[2];
    const float* audio_emb = (const float*)d_in[3];
    const float* Wqkv      = (const float*)d_in[4];
    const float* b_qkv     = (const float*)d_in[5];
    const float* Wo        = (const float*)d_in[6];
    const float* b_o       = (const float*)d_in[7];
    const float* W1        = (const float*)d_in[8];
    const float* b1        = (const float*)d_in[9];
    const float* W2        = (const float*)d_in[10];
    const float* b2        = (const float*)d_in[11];
    const float* ln1_w     = (const float*)d_in[12];
    const float* ln1_b     = (const float*)d_in[13];
    const float* ln2_w     = (const float*)d_in[14];
    const float* ln2_b     = (const float*)d_in[15];
    const float* lnf_w     = (const float*)d_in[16];
    const float* lnf_b     = (const float*)d_in[17];
    const float* proj_w    = (const float*)d_in[18];

    float *tmpP, *logitsP;
    __nv_bfloat16 *hbP, *qkvbP, *attnbP, *ffbP, *xbP, *WqkvP, *WoP, *W1P, *W2P, *projP;
    cudaGetSymbolAddress((void**)&hbP, g_hb);
    cudaGetSymbolAddress((void**)&qkvbP, g_qkvb);
    cudaGetSymbolAddress((void**)&attnbP, g_attnb);
    cudaGetSymbolAddress((void**)&tmpP, g_tmp);
    cudaGetSymbolAddress((void**)&ffbP, g_ffb);
    cudaGetSymbolAddress((void**)&xbP, g_xb);
    cudaGetSymbolAddress((void**)&logitsP, g_logits);
    cudaGetSymbolAddress((void**)&WqkvP, g_Wqkv);
    cudaGetSymbolAddress((void**)&WoP, g_Wo);
    cudaGetSymbolAddress((void**)&W1P, g_W1);
    cudaGetSymbolAddress((void**)&W2P, g_W2);
    cudaGetSymbolAddress((void**)&projP, g_proj);

    cudaFuncSetAttribute(gemm_mma<1,0,1>, cudaFuncAttributeMaxDynamicSharedMemorySize, GEMM_SMEM);
    cudaFuncSetAttribute(gemm_mma<1,1,1>, cudaFuncAttributeMaxDynamicSharedMemorySize, GEMM_SMEM);
    cudaFuncSetAttribute(gemm_mma64<0,1>, cudaFuncAttributeMaxDynamicSharedMemorySize, GEMM64_SMEM);
    cudaFuncSetAttribute(gemm_mma64<0,0>, cudaFuncAttributeMaxDynamicSharedMemorySize, GEMM64_SMEM);
    cudaFuncSetAttribute(flash_attn, cudaFuncAttributeMaxDynamicSharedMemorySize, FLASH_SMEM);

    wcast_all<<<2048, 256>>>(Wqkv, Wo, W1, W2);
    projcast<<<DD, 256>>>(proj_w, projP);

    embed_kernel<<<MROWS, 256>>>(tokens, codes, tok_emb, audio_emb);

    for (int l = 0; l < NLAYER; l++) {
        gemm_mma<1,0,1><<<dim3(3*DD/128, MROWS/128), 256, GEMM_SMEM>>>(
            qkvbP, hbP, WqkvP + (size_t)l*DD*3*DD, b_qkv + (size_t)l*3*DD, MROWS, DD, 3*DD);
        flash_attn<<<dim3(SS/128, BB*NH), 256, FLASH_SMEM>>>(qkvbP);
        gemm_mma64<0,1><<<dim3(DD/128, MROWS/64), 256, GEMM64_SMEM>>>(
            tmpP, attnbP, WoP + (size_t)l*DD*DD, b_o + (size_t)l*DD, MROWS, DD, DD);
        add_ln2<<<MROWS, 256>>>(tmpP, ln1_w + l*DD, ln1_b + l*DD);
        gemm_mma<1,1,1><<<dim3(FFD/128, MROWS/128), 256, GEMM_SMEM>>>(
            ffbP, hbP, W1P + (size_t)l*DD*FFD, b1 + (size_t)l*FFD, MROWS, DD, FFD);
        gemm_mma64<0,1><<<dim3(DD/128, MROWS/64), 256, GEMM64_SMEM>>>(
            tmpP, ffbP, W2P + (size_t)l*FFD*DD, b2 + (size_t)l*DD, MROWS, FFD, DD);
        add_ln2<<<MROWS, 256>>>(tmpP, ln2_w + l*DD, ln2_b + l*DD);
    }

    lnf_gather<<<PROWS, 256>>>(lnf_w, lnf_b);
    gemm_mma64<0,0><<<dim3(NPAD/128, PROWS/64), 256, GEMM64_SMEM>>>(
        logitsP, xbP, projP, nullptr, PROWS, DD, NPAD);
    nll_kernel<<<PROWS, 256>>>(codes);
    mean_kernel<<<1, 256>>>((float*)d_out);
}

// round 15
// speedup vs baseline: 1.0669x; 1.0399x over previous
#include <cuda_runtime.h>
#include <cuda_bf16.h>
#include <math.h>
#include <stdint.h>

#define BB 2
#define XL 256
#define CL 767
#define YL 768
#define SS 1024
#define DD 1024
#define FFD 4096
#define NLAYER 6
#define NH 16
#define DH 64
#define CVOC 1025
#define NPAD 1152
#define EOS_ID 1024
#define BOS_ID 1025
#define MROWS (BB*SS)
#define PROWS (BB*YL)

// ---------------- scratch (static device globals; no allocs) ----------------
__device__ float g_h[MROWS*DD];
__device__ __nv_bfloat16 g_hb[MROWS*DD];
__device__ __nv_bfloat16 g_qkvb[MROWS*3*DD];
__device__ __nv_bfloat16 g_attnb[MROWS*DD];
__device__ __nv_bfloat16 g_tmpb[MROWS*DD];          // bf16 GEMM partial (Wo/W2)
__device__ __nv_bfloat16 g_ffb[MROWS*FFD];
__device__ __nv_bfloat16 g_xb[PROWS*DD];
__device__ float g_logits[PROWS*NPAD];
__device__ float g_nll[PROWS];
// bf16 K-major weights [K,N] (no transpose)
__device__ __nv_bfloat16 g_Wqkv[NLAYER*DD*3*DD];
__device__ __nv_bfloat16 g_Wo[NLAYER*DD*DD];
__device__ __nv_bfloat16 g_W1[NLAYER*DD*FFD];
__device__ __nv_bfloat16 g_W2[NLAYER*FFD*DD];
__device__ __nv_bfloat16 g_proj[DD*NPAD];

// ---------------- helpers ----------------
__device__ __forceinline__ uint32_t smem_u32(const void* p) {
    uint32_t a;
    asm("{ .reg .u64 t; cvta.to.shared.u64 t, %1; cvt.u32.u64 %0, t; }" : "=r"(a) : "l"(p));
    return a;
}
__device__ __forceinline__ void cp16(void* smem_dst, const void* gsrc) {
    uint32_t s = smem_u32(smem_dst);
    asm volatile("cp.async.cg.shared.global [%0], [%1], 16;" :: "r"(s), "l"(gsrc));
}
__device__ __forceinline__ void cp_commit() { asm volatile("cp.async.commit_group;" ::: "memory"); }
__device__ __forceinline__ void cp_wait0()  { asm volatile("cp.async.wait_group 0;" ::: "memory"); }
__device__ __forceinline__ void cp_wait1()  { asm volatile("cp.async.wait_group 1;" ::: "memory"); }

__device__ __forceinline__ void ldm_x4(uint32_t* r, uint32_t addr) {
    asm volatile("ldmatrix.sync.aligned.m8n8.x4.shared.b16 {%0,%1,%2,%3}, [%4];"
        : "=r"(r[0]), "=r"(r[1]), "=r"(r[2]), "=r"(r[3]) : "r"(addr));
}
__device__ __forceinline__ void ldm_x4_t(uint32_t* r, uint32_t addr) {
    asm volatile("ldmatrix.sync.aligned.m8n8.x4.trans.shared.b16 {%0,%1,%2,%3}, [%4];"
        : "=r"(r[0]), "=r"(r[1]), "=r"(r[2]), "=r"(r[3]) : "r"(addr));
}
__device__ __forceinline__ void mma16816(float* c, const uint32_t* a, const uint32_t* b) {
    asm volatile("mma.sync.aligned.m16n8k16.row.col.f32.bf16.bf16.f32 "
        "{%0,%1,%2,%3}, {%4,%5,%6,%7}, {%8,%9}, {%0,%1,%2,%3};"
        : "+f"(c[0]), "+f"(c[1]), "+f"(c[2]), "+f"(c[3])
        : "r"(a[0]), "r"(a[1]), "r"(a[2]), "r"(a[3]), "r"(b[0]), "r"(b[1]));
}
__device__ __forceinline__ uint32_t pk(float x, float y) {
    __nv_bfloat162 p = __floats2bfloat162_rn(x, y);
    return *(uint32_t*)&p;
}

#define KCH 64
#define PADW 72                    // A-tile row pad (bf16 elems)
#define PADB 136                   // B-tile row pad (272B: conflict-free trans ldm)
#define ATILE_E (128*PADW)
#define BTILE_E (64*PADB)
#define GEMM_SMEM ((2*ATILE_E + 2*BTILE_E)*2 + 512)

// ---------------- HMMA bf16 GEMM (128x128 tile): C = A @ W (+bias)(+relu) ----------------
// grid (N/128, M/128), block 256 (8 warps: 2M x 4N; warp tile 64x32), 2 CTAs/SM, double-buffered
template<int OUT_BF16, int RELU, int HAS_BIAS>
__global__ void __launch_bounds__(256, 2) gemm_mma(void* __restrict__ Cv,
        const __nv_bfloat16* __restrict__ A, const __nv_bfloat16* __restrict__ W,
        const float* __restrict__ bias, int M, int K, int N) {
    extern __shared__ __nv_bfloat16 sm[];
    __nv_bfloat16* As = sm;                       // [2][128][PADW]
    __nv_bfloat16* Bs = sm + 2 * ATILE_E;         // [2][64][PADB]
    float* biasSm = (float*)(sm + 2 * ATILE_E + 2 * BTILE_E);

    int tid = threadIdx.x;
    int wid = tid >> 5, lane = tid & 31;
    int wm = wid >> 2, wn = wid & 3;
    int m0 = blockIdx.y * 128, n0 = blockIdx.x * 128;

    if (HAS_BIAS && tid < 128) biasSm[tid] = bias[n0 + tid];

    const __nv_bfloat16* gA = A + (size_t)m0 * K;
    const __nv_bfloat16* gB = W + n0;

    float acc[4][4][4];
#pragma unroll
    for (int i = 0; i < 4; i++)
#pragma unroll
        for (int j = 0; j < 4; j++)
#pragma unroll
            for (int q = 0; q < 4; q++) acc[i][j][q] = 0.f;

    const int nch = K / KCH;
    int ar = tid >> 3, ap = (tid & 7) * 8;
    int br = tid >> 4, bp = (tid & 15) * 8;

#pragma unroll
    for (int i = 0; i < 4; i++) {
        cp16(As + (ar + 32 * (i & 3)) * PADW + ap, gA + (size_t)(ar + 32 * (i & 3)) * K + ap);
        cp16(Bs + (br + 16 * (i & 3)) * PADB + bp, gB + (size_t)(br + 16 * (i & 3)) * N + bp);
    }
    cp_commit();

    int a_r = (lane & 7) + ((lane >> 3) & 1) * 8;
    int a_ch = (lane >> 4) * 8;

    for (int ic = 0; ic < nch; ic++) {
        int buf = ic & 1;
        cp_wait0();
        __syncthreads();
        if (ic + 1 < nch) {
            const __nv_bfloat16* gA1 = gA + (size_t)(ic + 1) * KCH;
            const __nv_bfloat16* gB1 = gB + (size_t)(ic + 1) * KCH * N;
            __nv_bfloat16* dA = As + (buf ^ 1) * ATILE_E;
            __nv_bfloat16* dB = Bs + (buf ^ 1) * BTILE_E;
#pragma unroll
            for (int i = 0; i < 4; i++) {
                cp16(dA + (ar + 32 * i) * PADW + ap, gA1 + (size_t)(ar + 32 * i) * K + ap);
                cp16(dB + (br + 16 * i) * PADB + bp, gB1 + (size_t)(br + 16 * i) * N + bp);
            }
            cp_commit();
        }

        const __nv_bfloat16* As_ = As + buf * ATILE_E;
        const __nv_bfloat16* Bs_ = Bs + buf * BTILE_E;
#pragma unroll
        for (int ks = 0; ks < 4; ks++) {
            uint32_t a[4][4], b[2][4];
#pragma unroll
            for (int mi = 0; mi < 4; mi++)
                ldm_x4(a[mi], smem_u32(As_ + (size_t)(wm * 64 + mi * 16 + a_r) * PADW + ks * 16 + a_ch));
#pragma unroll
            for (int ni2 = 0; ni2 < 2; ni2++)
                ldm_x4_t(b[ni2], smem_u32(Bs_ + (size_t)(ks * 16 + (lane & 15)) * PADB + wn * 32 + ni2 * 16 + (lane >> 4) * 8));
#pragma unroll
            for (int mi = 0; mi < 4; mi++)
#pragma unroll
                for (int ni = 0; ni < 4; ni++)
                    mma16816(acc[mi][ni], a[mi], b[ni >> 1] + (ni & 1) * 2);
        }
        __syncthreads();
    }

    int rg = lane >> 2, cg = (lane & 3) * 2;
#pragma unroll
    for (int mi = 0; mi < 4; mi++) {
#pragma unroll
        for (int ni = 0; ni < 4; ni++) {
            int colL = wn * 32 + ni * 8 + cg;
            int col = n0 + colL;
            float b0 = HAS_BIAS ? biasSm[colL] : 0.f;
            float b1 = HAS_BIAS ? biasSm[colL + 1] : 0.f;
#pragma unroll
            for (int rh = 0; rh < 2; rh++) {
                int row = m0 + wm * 64 + mi * 16 + rg + rh * 8;
                float v0 = acc[mi][ni][rh * 2 + 0] + b0;
                float v1 = acc[mi][ni][rh * 2 + 1] + b1;
                if (RELU) { v0 = fmaxf(v0, 0.f); v1 = fmaxf(v1, 0.f); }
                if (OUT_BF16) {
                    __nv_bfloat162 p = __floats2bfloat162_rn(v0, v1);
                    *(__nv_bfloat162*)((__nv_bfloat16*)Cv + (size_t)row * N + col) = p;
                } else {
                    *(float2*)((float*)Cv + (size_t)row * N + col) = make_float2(v0, v1);
                }
            }
        }
    }
}

// ---------------- fused flash attention ----------------
#define FLASH_SMEM ((128*PADW + 2*64*PADW + 2*64*PADW) * 2)
__global__ void __launch_bounds__(256, 2) flash_attn(const __nv_bfloat16* __restrict__ qkvb) {
    extern __shared__ __nv_bfloat16 fsm[];
    __nv_bfloat16* Qs = fsm;
    __nv_bfloat16* Ks = fsm + 128 * PADW;
    __nv_bfloat16* Vs = fsm + 128 * PADW + 2 * 64 * PADW;

    int bh = blockIdx.y;
    int b = bh / NH, h = bh % NH;
    int i0 = blockIdx.x * 128;
    int ntile = ((i0 < XL) ? XL : (i0 + 128)) / 64;

    int tid = threadIdx.x, w = tid >> 5, lane = tid & 31;
    const __nv_bfloat16* base = qkvb + (size_t)(b * SS) * 3 * DD + h * DH;

#pragma unroll
    for (int i = 0; i < 4; i++) {
        int c = tid + 256 * i;
        int row = c >> 3, cc = c & 7;
        cp16(Qs + row * PADW + cc * 8, base + (size_t)(i0 + row) * 3 * DD + cc * 8);
    }
#pragma unroll
    for (int i = 0; i < 2; i++) {
        int c = tid + 256 * i;
        int row = c >> 3, cc = c & 7;
        cp16(Ks + row * PADW + cc * 8, base + (size_t)row * 3 * DD + DD + cc * 8);
        cp16(Vs + row * PADW + cc * 8, base + (size_t)row * 3 * DD + 2 * DD + cc * 8);
    }
    cp_commit();

    float m0 = -1e30f, m1 = -1e30f, l0 = 0.f, l1 = 0.f;
    float o[8][4];
#pragma unroll
    for (int dt = 0; dt < 8; dt++)
#pragma unroll
        for (int q = 0; q < 4; q++) o[dt][q] = 0.f;

    int a_r = (lane & 7) + ((lane >> 3) & 1) * 8;
    int a_ch = (lane >> 4) * 8;
    int b_r = (lane & 7) + (lane >> 4) * 8;
    int b_ch = ((lane >> 3) & 1) * 8;
    int r0g = i0 + w * 16 + (lane >> 2);

    for (int t = 0; t < ntile; t++) {
        int buf = t & 1;
        if (t + 1 < ntile) {
            int j1 = (t + 1) * 64, nb = (t + 1) & 1;
#pragma unroll
            for (int i = 0; i < 2; i++) {
                int c = tid + 256 * i;
                int row = c >> 3, cc = c & 7;
                cp16(Ks + nb * 64 * PADW + row * PADW + cc * 8, base + (size_t)(j1 + row) * 3 * DD + DD + cc * 8);
                cp16(Vs + nb * 64 * PADW + row * PADW + cc * 8, base + (size_t)(j1 + row) * 3 * DD + 2 * DD + cc * 8);
            }
            cp_commit();
            cp_wait1();
        } else {
            cp_wait0();
        }
        __syncthreads();
        const __nv_bfloat16* K_ = Ks + buf * 64 * PADW;
        const __nv_bfloat16* V_ = Vs + buf * 64 * PADW;

        float s[8][4];
#pragma unroll
        for (int nt = 0; nt < 8; nt++)
#pragma unroll
            for (int q = 0; q < 4; q++) s[nt][q] = 0.f;
#pragma unroll
        for (int kd = 0; kd < 4; kd++) {
            uint32_t a[4];
            ldm_x4(a, smem_u32(Qs + (size_t)(w * 16 + a_r) * PADW + kd * 16 + a_ch));
            uint32_t bb[4][4];
#pragma unroll
            for (int nj = 0; nj < 4; nj++)
                ldm_x4(bb[nj], smem_u32(K_ + (size_t)(nj * 16 + b_r) * PADW + kd * 16 + b_ch));
#pragma unroll
            for (int nt = 0; nt < 8; nt++)
                mma16816(s[nt], a, bb[nt >> 1] + (nt & 1) * 2);
        }

        const float SC = 0.125f * 1.44269504f;
        int j0 = t * 64;
        if (i0 >= XL && j0 + 63 >= i0) {
#pragma unroll
            for (int nt = 0; nt < 8; nt++) {
                int j = j0 + nt * 8 + (lane & 3) * 2;
                s[nt][0] = (j     <= r0g)     ? s[nt][0] * SC : -1e30f;
                s[nt][1] = (j + 1 <= r0g)     ? s[nt][1] * SC : -1e30f;
                s[nt][2] = (j     <= r0g + 8) ? s[nt][2] * SC : -1e30f;
                s[nt][3] = (j + 1 <= r0g + 8) ? s[nt][3] * SC : -1e30f;
            }
        } else {
#pragma unroll
            for (int nt = 0; nt < 8; nt++)
#pragma unroll
                for (int q = 0; q < 4; q++) s[nt][q] *= SC;
        }

        float t0 = -1e30f, t1 = -1e30f;
#pragma unroll
        for (int nt = 0; nt < 8; nt++) {
            t0 = fmaxf(t0, fmaxf(s[nt][0], s[nt][1]));
            t1 = fmaxf(t1, fmaxf(s[nt][2], s[nt][3]));
        }
        t0 = fmaxf(t0, __shfl_xor_sync(0xffffffff, t0, 1));
        t0 = fmaxf(t0, __shfl_xor_sync(0xffffffff, t0, 2));
        t1 = fmaxf(t1, __shfl_xor_sync(0xffffffff, t1, 1));
        t1 = fmaxf(t1, __shfl_xor_sync(0xffffffff, t1, 2));
        float mn0 = fmaxf(m0, t0), mn1 = fmaxf(m1, t1);
        float al0 = exp2f(m0 - mn0), al1 = exp2f(m1 - mn1);
        m0 = mn0; m1 = mn1;
        float rs0 = 0.f, rs1 = 0.f;
#pragma unroll
        for (int nt = 0; nt < 8; nt++) {
            s[nt][0] = exp2f(s[nt][0] - m0); rs0 += s[nt][0];
            s[nt][1] = exp2f(s[nt][1] - m0); rs0 += s[nt][1];
            s[nt][2] = exp2f(s[nt][2] - m1); rs1 += s[nt][2];
            s[nt][3] = exp2f(s[nt][3] - m1); rs1 += s[nt][3];
        }
        rs0 += __shfl_xor_sync(0xffffffff, rs0, 1);
        rs0 += __shfl_xor_sync(0xffffffff, rs0, 2);
        rs1 += __shfl_xor_sync(0xffffffff, rs1, 1);
        rs1 += __shfl_xor_sync(0xffffffff, rs1, 2);
        l0 = l0 * al0 + rs0; l1 = l1 * al1 + rs1;
#pragma unroll
        for (int dt = 0; dt < 8; dt++) {
            o[dt][0] *= al0; o[dt][1] *= al0;
            o[dt][2] *= al1; o[dt][3] *= al1;
        }

        uint32_t pa[4][4];
#pragma unroll
        for (int kt = 0; kt < 4; kt++) {
            pa[kt][0] = pk(s[2 * kt][0], s[2 * kt][1]);
            pa[kt][1] = pk(s[2 * kt][2], s[2 * kt][3]);
            pa[kt][2] = pk(s[2 * kt + 1][0], s[2 * kt + 1][1]);
            pa[kt][3] = pk(s[2 * kt + 1][2], s[2 * kt + 1][3]);
        }

#pragma unroll
        for (int kt = 0; kt < 4; kt++) {
#pragma unroll
            for (int dv = 0; dv < 4; dv++) {
                uint32_t vb[4];
                ldm_x4_t(vb, smem_u32(V_ + (size_t)(kt * 16 + (lane & 15)) * PADW + dv * 16 + (lane >> 4) * 8));
                mma16816(o[dv * 2], pa[kt], vb);
                mma16816(o[dv * 2 + 1], pa[kt], vb + 2);
            }
        }
        __syncthreads();
    }

    float inv0 = 1.f / l0, inv1 = 1.f / l1;
#pragma unroll
    for (int dt = 0; dt < 8; dt++) {
        int cols = h * DH + dt * 8 + (lane & 3) * 2;
        __nv_bfloat162 p0 = __floats2bfloat162_rn(o[dt][0] * inv0, o[dt][1] * inv0);
        __nv_bfloat162 p1 = __floats2bfloat162_rn(o[dt][2] * inv1, o[dt][3] * inv1);
        *(__nv_bfloat162*)(g_attnb + (size_t)(b * SS + r0g) * DD + cols) = p0;
        *(__nv_bfloat162*)(g_attnb + (size_t)(b * SS + r0g + 8) * DD + cols) = p1;
    }
}

// ---------------- streaming fp32 -> bf16 cast (all weights in one launch) ----------------
#define N4_QKV (NLAYER*DD*3*DD/4)
#define N4_WO  (NLAYER*DD*DD/4)
#define N4_W1  (NLAYER*DD*FFD/4)
#define N4_W2  (NLAYER*FFD*DD/4)
__global__ void wcast_all(const float* __restrict__ Wqkv, const float* __restrict__ Wo,
                          const float* __restrict__ W1, const float* __restrict__ W2) {
    const int total = N4_QKV + N4_WO + N4_W1 + N4_W2;
    int stride = gridDim.x * blockDim.x;
    for (int i = blockIdx.x * blockDim.x + threadIdx.x; i < total; i += stride) {
        const float4* src;
        uint2* dst;
        int j = i;
        if (j < N4_QKV) { src = (const float4*)Wqkv; dst = (uint2*)g_Wqkv; }
        else if ((j -= N4_QKV) < N4_WO) { src = (const float4*)Wo; dst = (uint2*)g_Wo; }
        else if ((j -= N4_WO) < N4_W1) { src = (const float4*)W1; dst = (uint2*)g_W1; }
        else { j -= N4_W1; src = (const float4*)W2; dst = (uint2*)g_W2; }
        float4 v = src[j];
        __nv_bfloat162 p0 = __floats2bfloat162_rn(v.x, v.y);
        __nv_bfloat162 p1 = __floats2bfloat162_rn(v.z, v.w);
        dst[j] = make_uint2(*(uint32_t*)&p0, *(uint32_t*)&p1);
    }
}
__global__ void projcast(const float* __restrict__ W, __nv_bfloat16* __restrict__ o) {
    int k = blockIdx.x;
    for (int n = threadIdx.x; n < NPAD; n += blockDim.x)
        o[(size_t)k * NPAD + n] = (n < CVOC) ? __float2bfloat16(W[(size_t)k * CVOC + n]) : __nv_bfloat16(0.f);
}

// ---------------- embedding + sinusoidal PE ----------------
__global__ void embed_kernel(const int* __restrict__ tokens, const int* __restrict__ codes,
                             const float* __restrict__ tok_emb, const float* __restrict__ audio_emb) {
    int row = blockIdx.x;
    int b = row / SS, s = row % SS;
    const float* src; int pos;
    if (s < XL) { src = tok_emb + (size_t)tokens[b*XL + s] * DD; pos = s; }
    else {
        int sy = s - XL;
        int id = (sy == 0) ? BOS_ID : codes[b*CL + sy - 1];
        src = audio_emb + (size_t)id * DD; pos = sy;
    }
    float* dst = g_h + (size_t)row * DD;
    __nv_bfloat16* dstb = g_hb + (size_t)row * DD;
    const float kinv = 9.210340371976184f / (float)DD;
    for (int d = threadIdx.x; d < DD; d += blockDim.x) {
        float freq = expf(-(float)(d & ~1) * kinv);
        float ang = (float)pos * freq;
        float pe = (d & 1) ? cosf(ang) : sinf(ang);
        float v = src[d] + pe;
        dst[d] = v;
        dstb[d] = __float2bfloat16(v);
    }
}

// ---------------- h = LN(h + tmpb(bf16)); writes fp32 + bf16 ----------------
__global__ void __launch_bounds__(256) add_ln2(const __nv_bfloat16* __restrict__ p0,
        const float* __restrict__ w, const float* __restrict__ bvec) {
    __shared__ float red[8], red2[8];
    int row = blockIdx.x, tid = threadIdx.x, lane = tid & 31, wid = tid >> 5;

    float4 v = ((const float4*)(g_h + (size_t)row * DD))[tid];
    uint2 qb = ((const uint2*)(p0 + (size_t)row * DD))[tid];
    __nv_bfloat162 q0 = *(__nv_bfloat162*)&qb.x;
    __nv_bfloat162 q1 = *(__nv_bfloat162*)&qb.y;
    v.x += __bfloat162float(q0.x); v.y += __bfloat162float(q0.y);
    v.z += __bfloat162float(q1.x); v.w += __bfloat162float(q1.y);

    float s = v.x + v.y + v.z + v.w;
#pragma unroll
    for (int o = 16; o; o >>= 1) s += __shfl_xor_sync(0xffffffff, s, o);
    if (lane == 0) red[wid] = s;
    __syncthreads();
    float tot = 0.f;
#pragma unroll
    for (int i = 0; i < 8; i++) tot += red[i];
    float mu = tot * (1.f / DD);

    float dx = v.x - mu, dy = v.y - mu, dz = v.z - mu, dw = v.w - mu;
    float s2 = dx * dx + dy * dy + dz * dz + dw * dw;
#pragma unroll
    for (int o = 16; o; o >>= 1) s2 += __shfl_xor_sync(0xffffffff, s2, o);
    if (lane == 0) red2[wid] = s2;
    __syncthreads();
    float tot2 = 0.f;
#pragma unroll
    for (int i = 0; i < 8; i++) tot2 += red2[i];
    float rstd = rsqrtf(tot2 * (1.f / DD) + 1e-5f);

    float4 w4 = ((const float4*)w)[tid];
    float4 b4 = ((const float4*)bvec)[tid];
    float4 out;
    out.x = dx * rstd * w4.x + b4.x;
    out.y = dy * rstd * w4.y + b4.y;
    out.z = dz * rstd * w4.z + b4.z;
    out.w = dw * rstd * w4.w + b4.w;
    ((float4*)(g_h + (size_t)row * DD))[tid] = out;
    __nv_bfloat162 h0 = __floats2bfloat162_rn(out.x, out.y);
    __nv_bfloat162 h1 = __floats2bfloat162_rn(out.z, out.w);
    ((uint2*)(g_hb + (size_t)row * DD))[tid] = make_uint2(*(uint32_t*)&h0, *(uint32_t*)&h1);
}

// ---------------- final LN on audio rows only -> bf16 gather ----------------
__global__ void __launch_bounds__(256) lnf_gather(const float* __restrict__ w,
                                                  const float* __restrict__ bvec) {
    __shared__ float red[8], red2[8];
    int m = blockIdx.x, tid = threadIdx.x, lane = tid & 31, wid = tid >> 5;
    int b = m / YL, t = m % YL;

    float4 v = ((const float4*)(g_h + (size_t)(b * SS + XL + t) * DD))[tid];
    float s = v.x + v.y + v.z + v.w;
#pragma unroll
    for (int o = 16; o; o >>= 1) s += __shfl_xor_sync(0xffffffff, s, o);
    if (lane == 0) red[wid] = s;
    __syncthreads();
    float tot = 0.f;
#pragma unroll
    for (int i = 0; i < 8; i++) tot += red[i];
    float mu = tot * (1.f / DD);

    float dx = v.x - mu, dy = v.y - mu, dz = v.z - mu, dw = v.w - mu;
    float s2 = dx * dx + dy * dy + dz * dz + dw * dw;
#pragma unroll
    for (int o = 16; o; o >>= 1) s2 += __shfl_xor_sync(0xffffffff, s2, o);
    if (lane == 0) red2[wid] = s2;
    __syncthreads();
    float tot2 = 0.f;
#pragma unroll
    for (int i = 0; i < 8; i++) tot2 += red2[i];
    float rstd = rsqrtf(tot2 * (1.f / DD) + 1e-5f);

    float4 w4 = ((const float4*)w)[tid];
    float4 b4 = ((const float4*)bvec)[tid];
    __nv_bfloat162 h0 = __floats2bfloat162_rn(dx * rstd * w4.x + b4.x, dy * rstd * w4.y + b4.y);
    __nv_bfloat162 h1 = __floats2bfloat162_rn(dz * rstd * w4.z + b4.z, dw * rstd * w4.w + b4.w);
    ((uint2*)(g_xb + (size_t)m * DD))[tid] = make_uint2(*(uint32_t*)&h0, *(uint32_t*)&h1);
}

// ---------------- per-row NLL ----------------
__device__ __forceinline__ float blk_reduce_max(float v, float* red) {
    int t = threadIdx.x;
    red[t] = v; __syncthreads();
    for (int s = 128; s > 0; s >>= 1) { if (t < s) red[t] = fmaxf(red[t], red[t + s]); __syncthreads(); }
    float r = red[0]; __syncthreads();
    return r;
}
__device__ __forceinline__ float blk_reduce_sum(float v, float* red) {
    int t = threadIdx.x;
    red[t] = v; __syncthreads();
    for (int s = 128; s > 0; s >>= 1) { if (t < s) red[t] += red[t + s]; __syncthreads(); }
    float r = red[0]; __syncthreads();
    return r;
}
__global__ void nll_kernel(const int* __restrict__ codes) {
    __shared__ float red[256];
    int m = blockIdx.x;
    int b = m / YL, t = m % YL;
    const float* row = g_logits + (size_t)m * NPAD;
    int tid = threadIdx.x;

    float lmax = -1e30f;
    for (int j = tid; j < CVOC; j += 256) lmax = fmaxf(lmax, row[j]);
    lmax = blk_reduce_max(lmax, red);
    float lsum = 0.f;
    for (int j = tid; j < CVOC; j += 256) lsum += expf(row[j] - lmax);
    lsum = blk_reduce_sum(lsum, red);
    if (tid == 0) {
        int tgt = (t < CL) ? codes[b * CL + t] : EOS_ID;
        g_nll[m] = lmax + logf(lsum) - row[tgt];
    }
}

__global__ void mean_kernel(float* __restrict__ out) {
    __shared__ float red[256];
    int tid = threadIdx.x;
    float s = 0.f;
    for (int i = tid; i < PROWS; i += 256) s += g_nll[i];
    s = blk_reduce_sum(s, red);
    if (tid == 0) out[0] = s / (float)PROWS;
}

// ---------------- launch ----------------
extern "C" void kernel_launch(void* const* d_in, const int* in_sizes, int n_in,
                              void* d_out, int out_size) {
    const int*   tokens    = (const int*)d_in[0];
    const int*   codes     = (const int*)d_in[1];
    const float* tok_emb   = (const float*)d_in[2];
    const float* audio_emb = (const float*)d_in[3];
    const float* Wqkv      = (const float*)d_in[4];
    const float* b_qkv     = (const float*)d_in[5];
    const float* Wo        = (const float*)d_in[6];
    const float* b_o       = (const float*)d_in[7];
    const float* W1        = (const float*)d_in[8];
    const float* b1        = (const float*)d_in[9];
    const float* W2        = (const float*)d_in[10];
    const float* b2        = (const float*)d_in[11];
    const float* ln1_w     = (const float*)d_in[12];
    const float* ln1_b     = (const float*)d_in[13];
    const float* ln2_w     = (const float*)d_in[14];
    const float* ln2_b     = (const float*)d_in[15];
    const float* lnf_w     = (const float*)d_in[16];
    const float* lnf_b     = (const float*)d_in[17];
    const float* proj_w    = (const float*)d_in[18];

    float *logitsP;
    __nv_bfloat16 *hbP, *qkvbP, *attnbP, *tmpbP, *ffbP, *xbP, *WqkvP, *WoP, *W1P, *W2P, *projP;
    cudaGetSymbolAddress((void**)&hbP, g_hb);
    cudaGetSymbolAddress((void**)&qkvbP, g_qkvb);
    cudaGetSymbolAddress((void**)&attnbP, g_attnb);
    cudaGetSymbolAddress((void**)&tmpbP, g_tmpb);
    cudaGetSymbolAddress((void**)&ffbP, g_ffb);
    cudaGetSymbolAddress((void**)&xbP, g_xb);
    cudaGetSymbolAddress((void**)&logitsP, g_logits);
    cudaGetSymbolAddress((void**)&WqkvP, g_Wqkv);
    cudaGetSymbolAddress((void**)&WoP, g_Wo);
    cudaGetSymbolAddress((void**)&W1P, g_W1);
    cudaGetSymbolAddress((void**)&W2P, g_W2);
    cudaGetSymbolAddress((void**)&projP, g_proj);

    cudaFuncSetAttribute(gemm_mma<1,0,1>, cudaFuncAttributeMaxDynamicSharedMemorySize, GEMM_SMEM);
    cudaFuncSetAttribute(gemm_mma<1,1,1>, cudaFuncAttributeMaxDynamicSharedMemorySize, GEMM_SMEM);
    cudaFuncSetAttribute(gemm_mma<0,0,0>, cudaFuncAttributeMaxDynamicSharedMemorySize, GEMM_SMEM);
    cudaFuncSetAttribute(flash_attn, cudaFuncAttributeMaxDynamicSharedMemorySize, FLASH_SMEM);

    wcast_all<<<2048, 256>>>(Wqkv, Wo, W1, W2);
    projcast<<<DD, 256>>>(proj_w, projP);

    embed_kernel<<<MROWS, 256>>>(tokens, codes, tok_emb, audio_emb);

    for (int l = 0; l < NLAYER; l++) {
        gemm_mma<1,0,1><<<dim3(3*DD/128, MROWS/128), 256, GEMM_SMEM>>>(
            qkvbP, hbP, WqkvP + (size_t)l*DD*3*DD, b_qkv + (size_t)l*3*DD, MROWS, DD, 3*DD);
        flash_attn<<<dim3(SS/128, BB*NH), 256, FLASH_SMEM>>>(qkvbP);
        gemm_mma<1,0,1><<<dim3(DD/128, MROWS/128), 256, GEMM_SMEM>>>(
            tmpbP, attnbP, WoP + (size_t)l*DD*DD, b_o + (size_t)l*DD, MROWS, DD, DD);
        add_ln2<<<MROWS, 256>>>(tmpbP, ln1_w + l*DD, ln1_b + l*DD);
        gemm_mma<1,1,1><<<dim3(FFD/128, MROWS/128), 256, GEMM_SMEM>>>(
            ffbP, hbP, W1P + (size_t)l*DD*FFD, b1 + (size_t)l*FFD, MROWS, DD, FFD);
        gemm_mma<1,0,1><<<dim3(DD/128, MROWS/128), 256, GEMM_SMEM>>>(
            tmpbP, ffbP, W2P + (size_t)l*FFD*DD, b2 + (size_t)l*DD, MROWS, FFD, DD);
        add_ln2<<<MROWS, 256>>>(tmpbP, ln2_w + l*DD, ln2_b + l*DD);
    }

    lnf_gather<<<PROWS, 256>>>(lnf_w, lnf_b);
    gemm_mma<0,0,0><<<dim3(NPAD/128, PROWS/128), 256, GEMM_SMEM>>>(
        logitsP, xbP, projP, nullptr, PROWS, DD, NPAD);
    nll_kernel<<<PROWS, 256>>>(codes);
    mean_kernel<<<1, 256>>>((float*)d_out);
}

// round 16
// speedup vs baseline: 1.0888x; 1.0205x over previous
#include <cuda_runtime.h>
#include <cuda_bf16.h>
#include <math.h>
#include <stdint.h>

#define BB 2
#define XL 256
#define CL 767
#define YL 768
#define SS 1024
#define DD 1024
#define FFD 4096
#define NLAYER 6
#define NH 16
#define DH 64
#define CVOC 1025
#define NPAD 1152
#define EOS_ID 1024
#define BOS_ID 1025
#define MROWS (BB*SS)
#define PROWS (BB*YL)

// ---------------- scratch (static device globals; no allocs) ----------------
__device__ float g_h[MROWS*DD];
__device__ __nv_bfloat16 g_hb[MROWS*DD];
__device__ __nv_bfloat16 g_qkvb[MROWS*3*DD];
__device__ __nv_bfloat16 g_attnb[MROWS*DD];
__device__ __nv_bfloat16 g_tmpb[2*MROWS*DD];        // two bf16 split-K partials
__device__ __nv_bfloat16 g_ffb[MROWS*FFD];
__device__ __nv_bfloat16 g_xb[PROWS*DD];
__device__ float g_logits[2*PROWS*NPAD];            // two fp32 split-K partials
__device__ float g_nll[PROWS];
// bf16 K-major weights [K,N] (no transpose)
__device__ __nv_bfloat16 g_Wqkv[NLAYER*DD*3*DD];
__device__ __nv_bfloat16 g_Wo[NLAYER*DD*DD];
__device__ __nv_bfloat16 g_W1[NLAYER*DD*FFD];
__device__ __nv_bfloat16 g_W2[NLAYER*FFD*DD];
__device__ __nv_bfloat16 g_proj[DD*NPAD];

// ---------------- helpers ----------------
__device__ __forceinline__ uint32_t smem_u32(const void* p) {
    uint32_t a;
    asm("{ .reg .u64 t; cvta.to.shared.u64 t, %1; cvt.u32.u64 %0, t; }" : "=r"(a) : "l"(p));
    return a;
}
__device__ __forceinline__ void cp16(void* smem_dst, const void* gsrc) {
    uint32_t s = smem_u32(smem_dst);
    asm volatile("cp.async.cg.shared.global [%0], [%1], 16;" :: "r"(s), "l"(gsrc));
}
__device__ __forceinline__ void cp_commit() { asm volatile("cp.async.commit_group;" ::: "memory"); }
__device__ __forceinline__ void cp_wait0()  { asm volatile("cp.async.wait_group 0;" ::: "memory"); }
__device__ __forceinline__ void cp_wait1()  { asm volatile("cp.async.wait_group 1;" ::: "memory"); }

__device__ __forceinline__ void ldm_x4(uint32_t* r, uint32_t addr) {
    asm volatile("ldmatrix.sync.aligned.m8n8.x4.shared.b16 {%0,%1,%2,%3}, [%4];"
        : "=r"(r[0]), "=r"(r[1]), "=r"(r[2]), "=r"(r[3]) : "r"(addr));
}
__device__ __forceinline__ void ldm_x4_t(uint32_t* r, uint32_t addr) {
    asm volatile("ldmatrix.sync.aligned.m8n8.x4.trans.shared.b16 {%0,%1,%2,%3}, [%4];"
        : "=r"(r[0]), "=r"(r[1]), "=r"(r[2]), "=r"(r[3]) : "r"(addr));
}
__device__ __forceinline__ void mma16816(float* c, const uint32_t* a, const uint32_t* b) {
    asm volatile("mma.sync.aligned.m16n8k16.row.col.f32.bf16.bf16.f32 "
        "{%0,%1,%2,%3}, {%4,%5,%6,%7}, {%8,%9}, {%0,%1,%2,%3};"
        : "+f"(c[0]), "+f"(c[1]), "+f"(c[2]), "+f"(c[3])
        : "r"(a[0]), "r"(a[1]), "r"(a[2]), "r"(a[3]), "r"(b[0]), "r"(b[1]));
}
__device__ __forceinline__ uint32_t pk(float x, float y) {
    __nv_bfloat162 p = __floats2bfloat162_rn(x, y);
    return *(uint32_t*)&p;
}

#define KCH 64
#define PADW 72                    // A-tile row pad (bf16 elems)
#define PADB 136                   // B-tile row pad (272B: conflict-free trans ldm)
#define ATILE_E (128*PADW)
#define BTILE_E (64*PADB)
#define GEMM_SMEM ((2*ATILE_E + 2*BTILE_E)*2 + 512)

// ---------------- HMMA bf16 GEMM (128x128 tile): C = A @ W (+bias)(+relu), optional split-K ----------------
// grid (N/128, M/128, SPLITK), block 256 (8 warps: 2M x 4N; warp tile 64x32), 2 CTAs/SM
template<int OUT_BF16, int RELU, int HAS_BIAS, int SPLITK>
__global__ void __launch_bounds__(256, 2) gemm_mma(void* __restrict__ Cv,
        const __nv_bfloat16* __restrict__ A, const __nv_bfloat16* __restrict__ W,
        const float* __restrict__ bias, int M, int K, int N) {
    extern __shared__ __nv_bfloat16 sm[];
    __nv_bfloat16* As = sm;                       // [2][128][PADW]
    __nv_bfloat16* Bs = sm + 2 * ATILE_E;         // [2][64][PADB]
    float* biasSm = (float*)(sm + 2 * ATILE_E + 2 * BTILE_E);

    int tid = threadIdx.x;
    int wid = tid >> 5, lane = tid & 31;
    int wm = wid >> 2, wn = wid & 3;
    int m0 = blockIdx.y * 128, n0 = blockIdx.x * 128;
    int kLen = K / SPLITK;
    int kStart = (SPLITK > 1) ? blockIdx.z * kLen : 0;

    if (HAS_BIAS && tid < 128) biasSm[tid] = bias[n0 + tid];

    const __nv_bfloat16* gA = A + (size_t)m0 * K + kStart;
    const __nv_bfloat16* gB = W + (size_t)kStart * N + n0;

    float acc[4][4][4];
#pragma unroll
    for (int i = 0; i < 4; i++)
#pragma unroll
        for (int j = 0; j < 4; j++)
#pragma unroll
            for (int q = 0; q < 4; q++) acc[i][j][q] = 0.f;

    const int nch = kLen / KCH;
    int ar = tid >> 3, ap = (tid & 7) * 8;
    int br = tid >> 4, bp = (tid & 15) * 8;

#pragma unroll
    for (int i = 0; i < 4; i++) {
        cp16(As + (ar + 32 * i) * PADW + ap, gA + (size_t)(ar + 32 * i) * K + ap);
        cp16(Bs + (br + 16 * i) * PADB + bp, gB + (size_t)(br + 16 * i) * N + bp);
    }
    cp_commit();

    int a_r = (lane & 7) + ((lane >> 3) & 1) * 8;
    int a_ch = (lane >> 4) * 8;

    for (int ic = 0; ic < nch; ic++) {
        int buf = ic & 1;
        cp_wait0();
        __syncthreads();
        if (ic + 1 < nch) {
            const __nv_bfloat16* gA1 = gA + (size_t)(ic + 1) * KCH;
            const __nv_bfloat16* gB1 = gB + (size_t)(ic + 1) * KCH * N;
            __nv_bfloat16* dA = As + (buf ^ 1) * ATILE_E;
            __nv_bfloat16* dB = Bs + (buf ^ 1) * BTILE_E;
#pragma unroll
            for (int i = 0; i < 4; i++) {
                cp16(dA + (ar + 32 * i) * PADW + ap, gA1 + (size_t)(ar + 32 * i) * K + ap);
                cp16(dB + (br + 16 * i) * PADB + bp, gB1 + (size_t)(br + 16 * i) * N + bp);
            }
            cp_commit();
        }

        const __nv_bfloat16* As_ = As + buf * ATILE_E;
        const __nv_bfloat16* Bs_ = Bs + buf * BTILE_E;
#pragma unroll
        for (int ks = 0; ks < 4; ks++) {
            uint32_t a[4][4], b[2][4];
#pragma unroll
            for (int mi = 0; mi < 4; mi++)
                ldm_x4(a[mi], smem_u32(As_ + (size_t)(wm * 64 + mi * 16 + a_r) * PADW + ks * 16 + a_ch));
#pragma unroll
            for (int ni2 = 0; ni2 < 2; ni2++)
                ldm_x4_t(b[ni2], smem_u32(Bs_ + (size_t)(ks * 16 + (lane & 15)) * PADB + wn * 32 + ni2 * 16 + (lane >> 4) * 8));
#pragma unroll
            for (int mi = 0; mi < 4; mi++)
#pragma unroll
                for (int ni = 0; ni < 4; ni++)
                    mma16816(acc[mi][ni], a[mi], b[ni >> 1] + (ni & 1) * 2);
        }
        __syncthreads();
    }

    size_t poff = (SPLITK > 1) ? (size_t)blockIdx.z * M * N : 0;
    int rg = lane >> 2, cg = (lane & 3) * 2;
#pragma unroll
    for (int mi = 0; mi < 4; mi++) {
#pragma unroll
        for (int ni = 0; ni < 4; ni++) {
            int colL = wn * 32 + ni * 8 + cg;
            int col = n0 + colL;
            float b0 = HAS_BIAS ? biasSm[colL] : 0.f;
            float b1 = HAS_BIAS ? biasSm[colL + 1] : 0.f;
#pragma unroll
            for (int rh = 0; rh < 2; rh++) {
                int row = m0 + wm * 64 + mi * 16 + rg + rh * 8;
                float v0 = acc[mi][ni][rh * 2 + 0] + b0;
                float v1 = acc[mi][ni][rh * 2 + 1] + b1;
                if (RELU) { v0 = fmaxf(v0, 0.f); v1 = fmaxf(v1, 0.f); }
                if (OUT_BF16) {
                    __nv_bfloat162 p = __floats2bfloat162_rn(v0, v1);
                    *(__nv_bfloat162*)((__nv_bfloat16*)Cv + poff + (size_t)row * N + col) = p;
                } else {
                    *(float2*)((float*)Cv + poff + (size_t)row * N + col) = make_float2(v0, v1);
                }
            }
        }
    }
}

// ---------------- fused flash attention ----------------
#define FLASH_SMEM ((128*PADW + 2*64*PADW + 2*64*PADW) * 2)
__global__ void __launch_bounds__(256, 2) flash_attn(const __nv_bfloat16* __restrict__ qkvb) {
    extern __shared__ __nv_bfloat16 fsm[];
    __nv_bfloat16* Qs = fsm;
    __nv_bfloat16* Ks = fsm + 128 * PADW;
    __nv_bfloat16* Vs = fsm + 128 * PADW + 2 * 64 * PADW;

    int bh = blockIdx.y;
    int b = bh / NH, h = bh % NH;
    int i0 = blockIdx.x * 128;
    int ntile = ((i0 < XL) ? XL : (i0 + 128)) / 64;

    int tid = threadIdx.x, w = tid >> 5, lane = tid & 31;
    const __nv_bfloat16* base = qkvb + (size_t)(b * SS) * 3 * DD + h * DH;

#pragma unroll
    for (int i = 0; i < 4; i++) {
        int c = tid + 256 * i;
        int row = c >> 3, cc = c & 7;
        cp16(Qs + row * PADW + cc * 8, base + (size_t)(i0 + row) * 3 * DD + cc * 8);
    }
#pragma unroll
    for (int i = 0; i < 2; i++) {
        int c = tid + 256 * i;
        int row = c >> 3, cc = c & 7;
        cp16(Ks + row * PADW + cc * 8, base + (size_t)row * 3 * DD + DD + cc * 8);
        cp16(Vs + row * PADW + cc * 8, base + (size_t)row * 3 * DD + 2 * DD + cc * 8);
    }
    cp_commit();

    float m0 = -1e30f, m1 = -1e30f, l0 = 0.f, l1 = 0.f;
    float o[8][4];
#pragma unroll
    for (int dt = 0; dt < 8; dt++)
#pragma unroll
        for (int q = 0; q < 4; q++) o[dt][q] = 0.f;

    int a_r = (lane & 7) + ((lane >> 3) & 1) * 8;
    int a_ch = (lane >> 4) * 8;
    int b_r = (lane & 7) + (lane >> 4) * 8;
    int b_ch = ((lane >> 3) & 1) * 8;
    int r0g = i0 + w * 16 + (lane >> 2);

    for (int t = 0; t < ntile; t++) {
        int buf = t & 1;
        if (t + 1 < ntile) {
            int j1 = (t + 1) * 64, nb = (t + 1) & 1;
#pragma unroll
            for (int i = 0; i < 2; i++) {
                int c = tid + 256 * i;
                int row = c >> 3, cc = c & 7;
                cp16(Ks + nb * 64 * PADW + row * PADW + cc * 8, base + (size_t)(j1 + row) * 3 * DD + DD + cc * 8);
                cp16(Vs + nb * 64 * PADW + row * PADW + cc * 8, base + (size_t)(j1 + row) * 3 * DD + 2 * DD + cc * 8);
            }
            cp_commit();
            cp_wait1();
        } else {
            cp_wait0();
        }
        __syncthreads();
        const __nv_bfloat16* K_ = Ks + buf * 64 * PADW;
        const __nv_bfloat16* V_ = Vs + buf * 64 * PADW;

        float s[8][4];
#pragma unroll
        for (int nt = 0; nt < 8; nt++)
#pragma unroll
            for (int q = 0; q < 4; q++) s[nt][q] = 0.f;
#pragma unroll
        for (int kd = 0; kd < 4; kd++) {
            uint32_t a[4];
            ldm_x4(a, smem_u32(Qs + (size_t)(w * 16 + a_r) * PADW + kd * 16 + a_ch));
            uint32_t bb[4][4];
#pragma unroll
            for (int nj = 0; nj < 4; nj++)
                ldm_x4(bb[nj], smem_u32(K_ + (size_t)(nj * 16 + b_r) * PADW + kd * 16 + b_ch));
#pragma unroll
            for (int nt = 0; nt < 8; nt++)
                mma16816(s[nt], a, bb[nt >> 1] + (nt & 1) * 2);
        }

        const float SC = 0.125f * 1.44269504f;
        int j0 = t * 64;
        if (i0 >= XL && j0 + 63 >= i0) {
#pragma unroll
            for (int nt = 0; nt < 8; nt++) {
                int j = j0 + nt * 8 + (lane & 3) * 2;
                s[nt][0] = (j     <= r0g)     ? s[nt][0] * SC : -1e30f;
                s[nt][1] = (j + 1 <= r0g)     ? s[nt][1] * SC : -1e30f;
                s[nt][2] = (j     <= r0g + 8) ? s[nt][2] * SC : -1e30f;
                s[nt][3] = (j + 1 <= r0g + 8) ? s[nt][3] * SC : -1e30f;
            }
        } else {
#pragma unroll
            for (int nt = 0; nt < 8; nt++)
#pragma unroll
                for (int q = 0; q < 4; q++) s[nt][q] *= SC;
        }

        float t0 = -1e30f, t1 = -1e30f;
#pragma unroll
        for (int nt = 0; nt < 8; nt++) {
            t0 = fmaxf(t0, fmaxf(s[nt][0], s[nt][1]));
            t1 = fmaxf(t1, fmaxf(s[nt][2], s[nt][3]));
        }
        t0 = fmaxf(t0, __shfl_xor_sync(0xffffffff, t0, 1));
        t0 = fmaxf(t0, __shfl_xor_sync(0xffffffff, t0, 2));
        t1 = fmaxf(t1, __shfl_xor_sync(0xffffffff, t1, 1));
        t1 = fmaxf(t1, __shfl_xor_sync(0xffffffff, t1, 2));
        float mn0 = fmaxf(m0, t0), mn1 = fmaxf(m1, t1);
        float al0 = exp2f(m0 - mn0), al1 = exp2f(m1 - mn1);
        m0 = mn0; m1 = mn1;
        float rs0 = 0.f, rs1 = 0.f;
#pragma unroll
        for (int nt = 0; nt < 8; nt++) {
            s[nt][0] = exp2f(s[nt][0] - m0); rs0 += s[nt][0];
            s[nt][1] = exp2f(s[nt][1] - m0); rs0 += s[nt][1];
            s[nt][2] = exp2f(s[nt][2] - m1); rs1 += s[nt][2];
            s[nt][3] = exp2f(s[nt][3] - m1); rs1 += s[nt][3];
        }
        rs0 += __shfl_xor_sync(0xffffffff, rs0, 1);
        rs0 += __shfl_xor_sync(0xffffffff, rs0, 2);
        rs1 += __shfl_xor_sync(0xffffffff, rs1, 1);
        rs1 += __shfl_xor_sync(0xffffffff, rs1, 2);
        l0 = l0 * al0 + rs0; l1 = l1 * al1 + rs1;
#pragma unroll
        for (int dt = 0; dt < 8; dt++) {
            o[dt][0] *= al0; o[dt][1] *= al0;
            o[dt][2] *= al1; o[dt][3] *= al1;
        }

        uint32_t pa[4][4];
#pragma unroll
        for (int kt = 0; kt < 4; kt++) {
            pa[kt][0] = pk(s[2 * kt][0], s[2 * kt][1]);
            pa[kt][1] = pk(s[2 * kt][2], s[2 * kt][3]);
            pa[kt][2] = pk(s[2 * kt + 1][0], s[2 * kt + 1][1]);
            pa[kt][3] = pk(s[2 * kt + 1][2], s[2 * kt + 1][3]);
        }

#pragma unroll
        for (int kt = 0; kt < 4; kt++) {
#pragma unroll
            for (int dv = 0; dv < 4; dv++) {
                uint32_t vb[4];
                ldm_x4_t(vb, smem_u32(V_ + (size_t)(kt * 16 + (lane & 15)) * PADW + dv * 16 + (lane >> 4) * 8));
                mma16816(o[dv * 2], pa[kt], vb);
                mma16816(o[dv * 2 + 1], pa[kt], vb + 2);
            }
        }
        __syncthreads();
    }

    float inv0 = 1.f / l0, inv1 = 1.f / l1;
#pragma unroll
    for (int dt = 0; dt < 8; dt++) {
        int cols = h * DH + dt * 8 + (lane & 3) * 2;
        __nv_bfloat162 p0 = __floats2bfloat162_rn(o[dt][0] * inv0, o[dt][1] * inv0);
        __nv_bfloat162 p1 = __floats2bfloat162_rn(o[dt][2] * inv1, o[dt][3] * inv1);
        *(__nv_bfloat162*)(g_attnb + (size_t)(b * SS + r0g) * DD + cols) = p0;
        *(__nv_bfloat162*)(g_attnb + (size_t)(b * SS + r0g + 8) * DD + cols) = p1;
    }
}

// ---------------- streaming fp32 -> bf16 cast (all weights in one launch) ----------------
#define N4_QKV (NLAYER*DD*3*DD/4)
#define N4_WO  (NLAYER*DD*DD/4)
#define N4_W1  (NLAYER*DD*FFD/4)
#define N4_W2  (NLAYER*FFD*DD/4)
__global__ void wcast_all(const float* __restrict__ Wqkv, const float* __restrict__ Wo,
                          const float* __restrict__ W1, const float* __restrict__ W2) {
    const int total = N4_QKV + N4_WO + N4_W1 + N4_W2;
    int stride = gridDim.x * blockDim.x;
    for (int i = blockIdx.x * blockDim.x + threadIdx.x; i < total; i += stride) {
        const float4* src;
        uint2* dst;
        int j = i;
        if (j < N4_QKV) { src = (const float4*)Wqkv; dst = (uint2*)g_Wqkv; }
        else if ((j -= N4_QKV) < N4_WO) { src = (const float4*)Wo; dst = (uint2*)g_Wo; }
        else if ((j -= N4_WO) < N4_W1) { src = (const float4*)W1; dst = (uint2*)g_W1; }
        else { j -= N4_W1; src = (const float4*)W2; dst = (uint2*)g_W2; }
        float4 v = src[j];
        __nv_bfloat162 p0 = __floats2bfloat162_rn(v.x, v.y);
        __nv_bfloat162 p1 = __floats2bfloat162_rn(v.z, v.w);
        dst[j] = make_uint2(*(uint32_t*)&p0, *(uint32_t*)&p1);
    }
}
__global__ void projcast(const float* __restrict__ W, __nv_bfloat16* __restrict__ o) {
    int k = blockIdx.x;
    for (int n = threadIdx.x; n < NPAD; n += blockDim.x)
        o[(size_t)k * NPAD + n] = (n < CVOC) ? __float2bfloat16(W[(size_t)k * CVOC + n]) : __nv_bfloat16(0.f);
}

// ---------------- embedding + sinusoidal PE ----------------
__global__ void embed_kernel(const int* __restrict__ tokens, const int* __restrict__ codes,
                             const float* __restrict__ tok_emb, const float* __restrict__ audio_emb) {
    int row = blockIdx.x;
    int b = row / SS, s = row % SS;
    const float* src; int pos;
    if (s < XL) { src = tok_emb + (size_t)tokens[b*XL + s] * DD; pos = s; }
    else {
        int sy = s - XL;
        int id = (sy == 0) ? BOS_ID : codes[b*CL + sy - 1];
        src = audio_emb + (size_t)id * DD; pos = sy;
    }
    float* dst = g_h + (size_t)row * DD;
    __nv_bfloat16* dstb = g_hb + (size_t)row * DD;
    const float kinv = 9.210340371976184f / (float)DD;
    for (int d = threadIdx.x; d < DD; d += blockDim.x) {
        float freq = expf(-(float)(d & ~1) * kinv);
        float ang = (float)pos * freq;
        float pe = (d & 1) ? cosf(ang) : sinf(ang);
        float v = src[d] + pe;
        dst[d] = v;
        dstb[d] = __float2bfloat16(v);
    }
}

// ---------------- h = LN(h + p0 + p1 + bias); writes fp32 + bf16 ----------------
__global__ void __launch_bounds__(256) add_ln3(const __nv_bfloat16* __restrict__ p0,
        const __nv_bfloat16* __restrict__ p1, const float* __restrict__ bias,
        const float* __restrict__ w, const float* __restrict__ bvec) {
    __shared__ float red[8], red2[8];
    int row = blockIdx.x, tid = threadIdx.x, lane = tid & 31, wid = tid >> 5;

    float4 v = ((const float4*)(g_h + (size_t)row * DD))[tid];
    uint2 qa = ((const uint2*)(p0 + (size_t)row * DD))[tid];
    uint2 qb = ((const uint2*)(p1 + (size_t)row * DD))[tid];
    float4 bs = ((const float4*)bias)[tid];
    __nv_bfloat162 a0 = *(__nv_bfloat162*)&qa.x, a1 = *(__nv_bfloat162*)&qa.y;
    __nv_bfloat162 b0 = *(__nv_bfloat162*)&qb.x, b1 = *(__nv_bfloat162*)&qb.y;
    v.x += __bfloat162float(a0.x) + __bfloat162float(b0.x) + bs.x;
    v.y += __bfloat162float(a0.y) + __bfloat162float(b0.y) + bs.y;
    v.z += __bfloat162float(a1.x) + __bfloat162float(b1.x) + bs.z;
    v.w += __bfloat162float(a1.y) + __bfloat162float(b1.y) + bs.w;

    float s = v.x + v.y + v.z + v.w;
#pragma unroll
    for (int o = 16; o; o >>= 1) s += __shfl_xor_sync(0xffffffff, s, o);
    if (lane == 0) red[wid] = s;
    __syncthreads();
    float tot = 0.f;
#pragma unroll
    for (int i = 0; i < 8; i++) tot += red[i];
    float mu = tot * (1.f / DD);

    float dx = v.x - mu, dy = v.y - mu, dz = v.z - mu, dw = v.w - mu;
    float s2 = dx * dx + dy * dy + dz * dz + dw * dw;
#pragma unroll
    for (int o = 16; o; o >>= 1) s2 += __shfl_xor_sync(0xffffffff, s2, o);
    if (lane == 0) red2[wid] = s2;
    __syncthreads();
    float tot2 = 0.f;
#pragma unroll
    for (int i = 0; i < 8; i++) tot2 += red2[i];
    float rstd = rsqrtf(tot2 * (1.f / DD) + 1e-5f);

    float4 w4 = ((const float4*)w)[tid];
    float4 b4 = ((const float4*)bvec)[tid];
    float4 out;
    out.x = dx * rstd * w4.x + b4.x;
    out.y = dy * rstd * w4.y + b4.y;
    out.z = dz * rstd * w4.z + b4.z;
    out.w = dw * rstd * w4.w + b4.w;
    ((float4*)(g_h + (size_t)row * DD))[tid] = out;
    __nv_bfloat162 h0 = __floats2bfloat162_rn(out.x, out.y);
    __nv_bfloat162 h1 = __floats2bfloat162_rn(out.z, out.w);
    ((uint2*)(g_hb + (size_t)row * DD))[tid] = make_uint2(*(uint32_t*)&h0, *(uint32_t*)&h1);
}

// ---------------- final LN on audio rows only -> bf16 gather ----------------
__global__ void __launch_bounds__(256) lnf_gather(const float* __restrict__ w,
                                                  const float* __restrict__ bvec) {
    __shared__ float red[8], red2[8];
    int m = blockIdx.x, tid = threadIdx.x, lane = tid & 31, wid = tid >> 5;
    int b = m / YL, t = m % YL;

    float4 v = ((const float4*)(g_h + (size_t)(b * SS + XL + t) * DD))[tid];
    float s = v.x + v.y + v.z + v.w;
#pragma unroll
    for (int o = 16; o; o >>= 1) s += __shfl_xor_sync(0xffffffff, s, o);
    if (lane == 0) red[wid] = s;
    __syncthreads();
    float tot = 0.f;
#pragma unroll
    for (int i = 0; i < 8; i++) tot += red[i];
    float mu = tot * (1.f / DD);

    float dx = v.x - mu, dy = v.y - mu, dz = v.z - mu, dw = v.w - mu;
    float s2 = dx * dx + dy * dy + dz * dz + dw * dw;
#pragma unroll
    for (int o = 16; o; o >>= 1) s2 += __shfl_xor_sync(0xffffffff, s2, o);
    if (lane == 0) red2[wid] = s2;
    __syncthreads();
    float tot2 = 0.f;
#pragma unroll
    for (int i = 0; i < 8; i++) tot2 += red2[i];
    float rstd = rsqrtf(tot2 * (1.f / DD) + 1e-5f);

    float4 w4 = ((const float4*)w)[tid];
    float4 b4 = ((const float4*)bvec)[tid];
    __nv_bfloat162 h0 = __floats2bfloat162_rn(dx * rstd * w4.x + b4.x, dy * rstd * w4.y + b4.y);
    __nv_bfloat162 h1 = __floats2bfloat162_rn(dz * rstd * w4.z + b4.z, dw * rstd * w4.w + b4.w);
    ((uint2*)(g_xb + (size_t)m * DD))[tid] = make_uint2(*(uint32_t*)&h0, *(uint32_t*)&h1);
}

// ---------------- per-row NLL (sums two fp32 split-K logit partials) ----------------
__device__ __forceinline__ float blk_reduce_max(float v, float* red) {
    int t = threadIdx.x;
    red[t] = v; __syncthreads();
    for (int s = 128; s > 0; s >>= 1) { if (t < s) red[t] = fmaxf(red[t], red[t + s]); __syncthreads(); }
    float r = red[0]; __syncthreads();
    return r;
}
__device__ __forceinline__ float blk_reduce_sum(float v, float* red) {
    int t = threadIdx.x;
    red[t] = v; __syncthreads();
    for (int s = 128; s > 0; s >>= 1) { if (t < s) red[t] += red[t + s]; __syncthreads(); }
    float r = red[0]; __syncthreads();
    return r;
}
__global__ void nll_kernel(const int* __restrict__ codes) {
    __shared__ float red[256];
    __shared__ float rowbuf[CVOC];
    int m = blockIdx.x;
    int b = m / YL, t = m % YL;
    const float* r0 = g_logits + (size_t)m * NPAD;
    const float* r1 = g_logits + (size_t)PROWS * NPAD + (size_t)m * NPAD;
    int tid = threadIdx.x;

    float lmax = -1e30f;
    for (int j = tid; j < CVOC; j += 256) {
        float v = r0[j] + r1[j];
        rowbuf[j] = v;
        lmax = fmaxf(lmax, v);
    }
    lmax = blk_reduce_max(lmax, red);
    float lsum = 0.f;
    for (int j = tid; j < CVOC; j += 256) lsum += expf(rowbuf[j] - lmax);
    lsum = blk_reduce_sum(lsum, red);
    if (tid == 0) {
        int tgt = (t < CL) ? codes[b * CL + t] : EOS_ID;
        g_nll[m] = lmax + logf(lsum) - rowbuf[tgt];
    }
}

__global__ void mean_kernel(float* __restrict__ out) {
    __shared__ float red[256];
    int tid = threadIdx.x;
    float s = 0.f;
    for (int i = tid; i < PROWS; i += 256) s += g_nll[i];
    s = blk_reduce_sum(s, red);
    if (tid == 0) out[0] = s / (float)PROWS;
}

// ---------------- launch ----------------
extern "C" void kernel_launch(void* const* d_in, const int* in_sizes, int n_in,
                              void* d_out, int out_size) {
    const int*   tokens    = (const int*)d_in[0];
    const int*   codes     = (const int*)d_in[1];
    const float* tok_emb   = (const float*)d_in[2];
    const float* audio_emb = (const float*)d_in[3];
    const float* Wqkv      = (const float*)d_in[4];
    const float* b_qkv     = (const float*)d_in[5];
    const float* Wo        = (const float*)d_in[6];
    const float* b_o       = (const float*)d_in[7];
    const float* W1        = (const float*)d_in[8];
    const float* b1        = (const float*)d_in[9];
    const float* W2        = (const float*)d_in[10];
    const float* b2        = (const float*)d_in[11];
    const float* ln1_w     = (const float*)d_in[12];
    const float* ln1_b     = (const float*)d_in[13];
    const float* ln2_w     = (const float*)d_in[14];
    const float* ln2_b     = (const float*)d_in[15];
    const float* lnf_w     = (const float*)d_in[16];
    const float* lnf_b     = (const float*)d_in[17];
    const float* proj_w    = (const float*)d_in[18];

    float *logitsP;
    __nv_bfloat16 *hbP, *qkvbP, *attnbP, *tmpbP, *ffbP, *xbP, *WqkvP, *WoP, *W1P, *W2P, *projP;
    cudaGetSymbolAddress((void**)&hbP, g_hb);
    cudaGetSymbolAddress((void**)&qkvbP, g_qkvb);
    cudaGetSymbolAddress((void**)&attnbP, g_attnb);
    cudaGetSymbolAddress((void**)&tmpbP, g_tmpb);
    cudaGetSymbolAddress((void**)&ffbP, g_ffb);
    cudaGetSymbolAddress((void**)&xbP, g_xb);
    cudaGetSymbolAddress((void**)&logitsP, g_logits);
    cudaGetSymbolAddress((void**)&WqkvP, g_Wqkv);
    cudaGetSymbolAddress((void**)&WoP, g_Wo);
    cudaGetSymbolAddress((void**)&W1P, g_W1);
    cudaGetSymbolAddress((void**)&W2P, g_W2);
    cudaGetSymbolAddress((void**)&projP, g_proj);

    cudaFuncSetAttribute(gemm_mma<1,0,1,1>, cudaFuncAttributeMaxDynamicSharedMemorySize, GEMM_SMEM);
    cudaFuncSetAttribute(gemm_mma<1,1,1,1>, cudaFuncAttributeMaxDynamicSharedMemorySize, GEMM_SMEM);
    cudaFuncSetAttribute(gemm_mma<1,0,0,2>, cudaFuncAttributeMaxDynamicSharedMemorySize, GEMM_SMEM);
    cudaFuncSetAttribute(gemm_mma<0,0,0,2>, cudaFuncAttributeMaxDynamicSharedMemorySize, GEMM_SMEM);
    cudaFuncSetAttribute(flash_attn, cudaFuncAttributeMaxDynamicSharedMemorySize, FLASH_SMEM);

    wcast_all<<<2048, 256>>>(Wqkv, Wo, W1, W2);
    projcast<<<DD, 256>>>(proj_w, projP);

    embed_kernel<<<MROWS, 256>>>(tokens, codes, tok_emb, audio_emb);

    for (int l = 0; l < NLAYER; l++) {
        gemm_mma<1,0,1,1><<<dim3(3*DD/128, MROWS/128, 1), 256, GEMM_SMEM>>>(
            qkvbP, hbP, WqkvP + (size_t)l*DD*3*DD, b_qkv + (size_t)l*3*DD, MROWS, DD, 3*DD);
        flash_attn<<<dim3(SS/128, BB*NH), 256, FLASH_SMEM>>>(qkvbP);
        gemm_mma<1,0,0,2><<<dim3(DD/128, MROWS/128, 2), 256, GEMM_SMEM>>>(
            tmpbP, attnbP, WoP + (size_t)l*DD*DD, nullptr, MROWS, DD, DD);
        add_ln3<<<MROWS, 256>>>(tmpbP, tmpbP + (size_t)MROWS*DD, b_o + (size_t)l*DD,
                                ln1_w + l*DD, ln1_b + l*DD);
        gemm_mma<1,1,1,1><<<dim3(FFD/128, MROWS/128, 1), 256, GEMM_SMEM>>>(
            ffbP, hbP, W1P + (size_t)l*DD*FFD, b1 + (size_t)l*FFD, MROWS, DD, FFD);
        gemm_mma<1,0,0,2><<<dim3(DD/128, MROWS/128, 2), 256, GEMM_SMEM>>>(
            tmpbP, ffbP, W2P + (size_t)l*FFD*DD, nullptr, MROWS, FFD, DD);
        add_ln3<<<MROWS, 256>>>(tmpbP, tmpbP + (size_t)MROWS*DD, b2 + (size_t)l*DD,
                                ln2_w + l*DD, ln2_b + l*DD);
    }

    lnf_gather<<<PROWS, 256>>>(lnf_w, lnf_b);
    gemm_mma<0,0,0,2><<<dim3(NPAD/128, PROWS/128, 2), 256, GEMM_SMEM>>>(
        logitsP, xbP, projP, nullptr, PROWS, DD, NPAD);
    nll_kernel<<<PROWS, 256>>>(codes);
    mean_kernel<<<1, 256>>>((float*)d_out);
}

// round 17
// speedup vs baseline: 1.0954x; 1.0061x over previous
#include <cuda_runtime.h>
#include <cuda_bf16.h>
#include <math.h>
#include <stdint.h>

#define BB 2
#define XL 256
#define CL 767
#define YL 768
#define SS 1024
#define DD 1024
#define FFD 4096
#define NLAYER 6
#define NH 16
#define DH 64
#define CVOC 1025
#define NPAD 1152
#define EOS_ID 1024
#define BOS_ID 1025
#define MROWS (BB*SS)
#define PROWS (BB*YL)

// ---------------- scratch (static device globals; no allocs) ----------------
__device__ __nv_bfloat16 g_hb[MROWS*DD];            // bf16 residual stream
__device__ __nv_bfloat16 g_qkvb[MROWS*3*DD];
__device__ __nv_bfloat16 g_attnb[MROWS*DD];
__device__ __nv_bfloat16 g_tmpb[2*MROWS*DD];        // two bf16 split-K partials
__device__ __nv_bfloat16 g_ffb[MROWS*FFD];
__device__ __nv_bfloat16 g_xb[PROWS*DD];
__device__ float g_logits[2*PROWS*NPAD];            // two fp32 split-K partials
__device__ float g_nll[PROWS];
// bf16 K-major weights [K,N] (no transpose)
__device__ __nv_bfloat16 g_Wqkv[NLAYER*DD*3*DD];
__device__ __nv_bfloat16 g_Wo[NLAYER*DD*DD];
__device__ __nv_bfloat16 g_W1[NLAYER*DD*FFD];
__device__ __nv_bfloat16 g_W2[NLAYER*FFD*DD];
__device__ __nv_bfloat16 g_proj[DD*NPAD];

// ---------------- helpers ----------------
__device__ __forceinline__ uint32_t smem_u32(const void* p) {
    uint32_t a;
    asm("{ .reg .u64 t; cvta.to.shared.u64 t, %1; cvt.u32.u64 %0, t; }" : "=r"(a) : "l"(p));
    return a;
}
__device__ __forceinline__ void cp16(void* smem_dst, const void* gsrc) {
    uint32_t s = smem_u32(smem_dst);
    asm volatile("cp.async.cg.shared.global [%0], [%1], 16;" :: "r"(s), "l"(gsrc));
}
__device__ __forceinline__ void cp_commit() { asm volatile("cp.async.commit_group;" ::: "memory"); }
__device__ __forceinline__ void cp_wait0()  { asm volatile("cp.async.wait_group 0;" ::: "memory"); }
__device__ __forceinline__ void cp_wait1()  { asm volatile("cp.async.wait_group 1;" ::: "memory"); }

__device__ __forceinline__ void ldm_x4(uint32_t* r, uint32_t addr) {
    asm volatile("ldmatrix.sync.aligned.m8n8.x4.shared.b16 {%0,%1,%2,%3}, [%4];"
        : "=r"(r[0]), "=r"(r[1]), "=r"(r[2]), "=r"(r[3]) : "r"(addr));
}
__device__ __forceinline__ void ldm_x4_t(uint32_t* r, uint32_t addr) {
    asm volatile("ldmatrix.sync.aligned.m8n8.x4.trans.shared.b16 {%0,%1,%2,%3}, [%4];"
        : "=r"(r[0]), "=r"(r[1]), "=r"(r[2]), "=r"(r[3]) : "r"(addr));
}
__device__ __forceinline__ void mma16816(float* c, const uint32_t* a, const uint32_t* b) {
    asm volatile("mma.sync.aligned.m16n8k16.row.col.f32.bf16.bf16.f32 "
        "{%0,%1,%2,%3}, {%4,%5,%6,%7}, {%8,%9}, {%0,%1,%2,%3};"
        : "+f"(c[0]), "+f"(c[1]), "+f"(c[2]), "+f"(c[3])
        : "r"(a[0]), "r"(a[1]), "r"(a[2]), "r"(a[3]), "r"(b[0]), "r"(b[1]));
}
__device__ __forceinline__ uint32_t pk(float x, float y) {
    __nv_bfloat162 p = __floats2bfloat162_rn(x, y);
    return *(uint32_t*)&p;
}

#define KCH 64
#define PADW 72                    // A-tile row pad (bf16 elems)
#define PADB 136                   // B-tile row pad (272B: conflict-free trans ldm)
#define ATILE_E (128*PADW)
#define BTILE_E (64*PADB)
#define GEMM_SMEM ((2*ATILE_E + 2*BTILE_E)*2 + 512)

// ---------------- HMMA bf16 GEMM (128x128 tile): C = A @ W (+bias)(+relu), optional split-K ----------------
// grid (N/128, M/128, SPLITK), block 256 (8 warps: 2M x 4N; warp tile 64x32), 2 CTAs/SM
template<int OUT_BF16, int RELU, int HAS_BIAS, int SPLITK>
__global__ void __launch_bounds__(256, 2) gemm_mma(void* __restrict__ Cv,
        const __nv_bfloat16* __restrict__ A, const __nv_bfloat16* __restrict__ W,
        const float* __restrict__ bias, int M, int K, int N) {
    extern __shared__ __nv_bfloat16 sm[];
    __nv_bfloat16* As = sm;                       // [2][128][PADW]
    __nv_bfloat16* Bs = sm + 2 * ATILE_E;         // [2][64][PADB]
    float* biasSm = (float*)(sm + 2 * ATILE_E + 2 * BTILE_E);

    int tid = threadIdx.x;
    int wid = tid >> 5, lane = tid & 31;
    int wm = wid >> 2, wn = wid & 3;
    int m0 = blockIdx.y * 128, n0 = blockIdx.x * 128;
    int kLen = K / SPLITK;
    int kStart = (SPLITK > 1) ? blockIdx.z * kLen : 0;

    if (HAS_BIAS && tid < 128) biasSm[tid] = bias[n0 + tid];

    const __nv_bfloat16* gA = A + (size_t)m0 * K + kStart;
    const __nv_bfloat16* gB = W + (size_t)kStart * N + n0;

    float acc[4][4][4];
#pragma unroll
    for (int i = 0; i < 4; i++)
#pragma unroll
        for (int j = 0; j < 4; j++)
#pragma unroll
            for (int q = 0; q < 4; q++) acc[i][j][q] = 0.f;

    const int nch = kLen / KCH;
    int ar = tid >> 3, ap = (tid & 7) * 8;
    int br = tid >> 4, bp = (tid & 15) * 8;

#pragma unroll
    for (int i = 0; i < 4; i++) {
        cp16(As + (ar + 32 * i) * PADW + ap, gA + (size_t)(ar + 32 * i) * K + ap);
        cp16(Bs + (br + 16 * i) * PADB + bp, gB + (size_t)(br + 16 * i) * N + bp);
    }
    cp_commit();

    int a_r = (lane & 7) + ((lane >> 3) & 1) * 8;
    int a_ch = (lane >> 4) * 8;

    for (int ic = 0; ic < nch; ic++) {
        int buf = ic & 1;
        cp_wait0();
        __syncthreads();
        if (ic + 1 < nch) {
            const __nv_bfloat16* gA1 = gA + (size_t)(ic + 1) * KCH;
            const __nv_bfloat16* gB1 = gB + (size_t)(ic + 1) * KCH * N;
            __nv_bfloat16* dA = As + (buf ^ 1) * ATILE_E;
            __nv_bfloat16* dB = Bs + (buf ^ 1) * BTILE_E;
#pragma unroll
            for (int i = 0; i < 4; i++) {
                cp16(dA + (ar + 32 * i) * PADW + ap, gA1 + (size_t)(ar + 32 * i) * K + ap);
                cp16(dB + (br + 16 * i) * PADB + bp, gB1 + (size_t)(br + 16 * i) * N + bp);
            }
            cp_commit();
        }

        const __nv_bfloat16* As_ = As + buf * ATILE_E;
        const __nv_bfloat16* Bs_ = Bs + buf * BTILE_E;
#pragma unroll
        for (int ks = 0; ks < 4; ks++) {
            uint32_t a[4][4], b[2][4];
#pragma unroll
            for (int mi = 0; mi < 4; mi++)
                ldm_x4(a[mi], smem_u32(As_ + (size_t)(wm * 64 + mi * 16 + a_r) * PADW + ks * 16 + a_ch));
#pragma unroll
            for (int ni2 = 0; ni2 < 2; ni2++)
                ldm_x4_t(b[ni2], smem_u32(Bs_ + (size_t)(ks * 16 + (lane & 15)) * PADB + wn * 32 + ni2 * 16 + (lane >> 4) * 8));
#pragma unroll
            for (int mi = 0; mi < 4; mi++)
#pragma unroll
                for (int ni = 0; ni < 4; ni++)
                    mma16816(acc[mi][ni], a[mi], b[ni >> 1] + (ni & 1) * 2);
        }
        __syncthreads();
    }

    size_t poff = (SPLITK > 1) ? (size_t)blockIdx.z * M * N : 0;
    int rg = lane >> 2, cg = (lane & 3) * 2;
#pragma unroll
    for (int mi = 0; mi < 4; mi++) {
#pragma unroll
        for (int ni = 0; ni < 4; ni++) {
            int colL = wn * 32 + ni * 8 + cg;
            int col = n0 + colL;
            float b0 = HAS_BIAS ? biasSm[colL] : 0.f;
            float b1 = HAS_BIAS ? biasSm[colL + 1] : 0.f;
#pragma unroll
            for (int rh = 0; rh < 2; rh++) {
                int row = m0 + wm * 64 + mi * 16 + rg + rh * 8;
                float v0 = acc[mi][ni][rh * 2 + 0] + b0;
                float v1 = acc[mi][ni][rh * 2 + 1] + b1;
                if (RELU) { v0 = fmaxf(v0, 0.f); v1 = fmaxf(v1, 0.f); }
                if (OUT_BF16) {
                    __nv_bfloat162 p = __floats2bfloat162_rn(v0, v1);
                    *(__nv_bfloat162*)((__nv_bfloat16*)Cv + poff + (size_t)row * N + col) = p;
                } else {
                    *(float2*)((float*)Cv + poff + (size_t)row * N + col) = make_float2(v0, v1);
                }
            }
        }
    }
}

// ---------------- fused flash attention ----------------
#define FLASH_SMEM ((128*PADW + 2*64*PADW + 2*64*PADW) * 2)
__global__ void __launch_bounds__(256, 2) flash_attn(const __nv_bfloat16* __restrict__ qkvb) {
    extern __shared__ __nv_bfloat16 fsm[];
    __nv_bfloat16* Qs = fsm;
    __nv_bfloat16* Ks = fsm + 128 * PADW;
    __nv_bfloat16* Vs = fsm + 128 * PADW + 2 * 64 * PADW;

    int bh = blockIdx.y;
    int b = bh / NH, h = bh % NH;
    int i0 = blockIdx.x * 128;
    int ntile = ((i0 < XL) ? XL : (i0 + 128)) / 64;

    int tid = threadIdx.x, w = tid >> 5, lane = tid & 31;
    const __nv_bfloat16* base = qkvb + (size_t)(b * SS) * 3 * DD + h * DH;

#pragma unroll
    for (int i = 0; i < 4; i++) {
        int c = tid + 256 * i;
        int row = c >> 3, cc = c & 7;
        cp16(Qs + row * PADW + cc * 8, base + (size_t)(i0 + row) * 3 * DD + cc * 8);
    }
#pragma unroll
    for (int i = 0; i < 2; i++) {
        int c = tid + 256 * i;
        int row = c >> 3, cc = c & 7;
        cp16(Ks + row * PADW + cc * 8, base + (size_t)row * 3 * DD + DD + cc * 8);
        cp16(Vs + row * PADW + cc * 8, base + (size_t)row * 3 * DD + 2 * DD + cc * 8);
    }
    cp_commit();

    float m0 = -1e30f, m1 = -1e30f, l0 = 0.f, l1 = 0.f;
    float o[8][4];
#pragma unroll
    for (int dt = 0; dt < 8; dt++)
#pragma unroll
        for (int q = 0; q < 4; q++) o[dt][q] = 0.f;

    int a_r = (lane & 7) + ((lane >> 3) & 1) * 8;
    int a_ch = (lane >> 4) * 8;
    int b_r = (lane & 7) + (lane >> 4) * 8;
    int b_ch = ((lane >> 3) & 1) * 8;
    int r0g = i0 + w * 16 + (lane >> 2);

    for (int t = 0; t < ntile; t++) {
        int buf = t & 1;
        if (t + 1 < ntile) {
            int j1 = (t + 1) * 64, nb = (t + 1) & 1;
#pragma unroll
            for (int i = 0; i < 2; i++) {
                int c = tid + 256 * i;
                int row = c >> 3, cc = c & 7;
                cp16(Ks + nb * 64 * PADW + row * PADW + cc * 8, base + (size_t)(j1 + row) * 3 * DD + DD + cc * 8);
                cp16(Vs + nb * 64 * PADW + row * PADW + cc * 8, base + (size_t)(j1 + row) * 3 * DD + 2 * DD + cc * 8);
            }
            cp_commit();
            cp_wait1();
        } else {
            cp_wait0();
        }
        __syncthreads();
        const __nv_bfloat16* K_ = Ks + buf * 64 * PADW;
        const __nv_bfloat16* V_ = Vs + buf * 64 * PADW;

        float s[8][4];
#pragma unroll
        for (int nt = 0; nt < 8; nt++)
#pragma unroll
            for (int q = 0; q < 4; q++) s[nt][q] = 0.f;
#pragma unroll
        for (int kd = 0; kd < 4; kd++) {
            uint32_t a[4];
            ldm_x4(a, smem_u32(Qs + (size_t)(w * 16 + a_r) * PADW + kd * 16 + a_ch));
            uint32_t bb[4][4];
#pragma unroll
            for (int nj = 0; nj < 4; nj++)
                ldm_x4(bb[nj], smem_u32(K_ + (size_t)(nj * 16 + b_r) * PADW + kd * 16 + b_ch));
#pragma unroll
            for (int nt = 0; nt < 8; nt++)
                mma16816(s[nt], a, bb[nt >> 1] + (nt & 1) * 2);
        }

        const float SC = 0.125f * 1.44269504f;
        int j0 = t * 64;
        if (i0 >= XL && j0 + 63 >= i0) {
#pragma unroll
            for (int nt = 0; nt < 8; nt++) {
                int j = j0 + nt * 8 + (lane & 3) * 2;
                s[nt][0] = (j     <= r0g)     ? s[nt][0] * SC : -1e30f;
                s[nt][1] = (j + 1 <= r0g)     ? s[nt][1] * SC : -1e30f;
                s[nt][2] = (j     <= r0g + 8) ? s[nt][2] * SC : -1e30f;
                s[nt][3] = (j + 1 <= r0g + 8) ? s[nt][3] * SC : -1e30f;
            }
        } else {
#pragma unroll
            for (int nt = 0; nt < 8; nt++)
#pragma unroll
                for (int q = 0; q < 4; q++) s[nt][q] *= SC;
        }

        float t0 = -1e30f, t1 = -1e30f;
#pragma unroll
        for (int nt = 0; nt < 8; nt++) {
            t0 = fmaxf(t0, fmaxf(s[nt][0], s[nt][1]));
            t1 = fmaxf(t1, fmaxf(s[nt][2], s[nt][3]));
        }
        t0 = fmaxf(t0, __shfl_xor_sync(0xffffffff, t0, 1));
        t0 = fmaxf(t0, __shfl_xor_sync(0xffffffff, t0, 2));
        t1 = fmaxf(t1, __shfl_xor_sync(0xffffffff, t1, 1));
        t1 = fmaxf(t1, __shfl_xor_sync(0xffffffff, t1, 2));
        float mn0 = fmaxf(m0, t0), mn1 = fmaxf(m1, t1);
        float al0 = exp2f(m0 - mn0), al1 = exp2f(m1 - mn1);
        m0 = mn0; m1 = mn1;
        float rs0 = 0.f, rs1 = 0.f;
#pragma unroll
        for (int nt = 0; nt < 8; nt++) {
            s[nt][0] = exp2f(s[nt][0] - m0); rs0 += s[nt][0];
            s[nt][1] = exp2f(s[nt][1] - m0); rs0 += s[nt][1];
            s[nt][2] = exp2f(s[nt][2] - m1); rs1 += s[nt][2];
            s[nt][3] = exp2f(s[nt][3] - m1); rs1 += s[nt][3];
        }
        rs0 += __shfl_xor_sync(0xffffffff, rs0, 1);
        rs0 += __shfl_xor_sync(0xffffffff, rs0, 2);
        rs1 += __shfl_xor_sync(0xffffffff, rs1, 1);
        rs1 += __shfl_xor_sync(0xffffffff, rs1, 2);
        l0 = l0 * al0 + rs0; l1 = l1 * al1 + rs1;
#pragma unroll
        for (int dt = 0; dt < 8; dt++) {
            o[dt][0] *= al0; o[dt][1] *= al0;
            o[dt][2] *= al1; o[dt][3] *= al1;
        }

        uint32_t pa[4][4];
#pragma unroll
        for (int kt = 0; kt < 4; kt++) {
            pa[kt][0] = pk(s[2 * kt][0], s[2 * kt][1]);
            pa[kt][1] = pk(s[2 * kt][2], s[2 * kt][3]);
            pa[kt][2] = pk(s[2 * kt + 1][0], s[2 * kt + 1][1]);
            pa[kt][3] = pk(s[2 * kt + 1][2], s[2 * kt + 1][3]);
        }

#pragma unroll
        for (int kt = 0; kt < 4; kt++) {
#pragma unroll
            for (int dv = 0; dv < 4; dv++) {
                uint32_t vb[4];
                ldm_x4_t(vb, smem_u32(V_ + (size_t)(kt * 16 + (lane & 15)) * PADW + dv * 16 + (lane >> 4) * 8));
                mma16816(o[dv * 2], pa[kt], vb);
                mma16816(o[dv * 2 + 1], pa[kt], vb + 2);
            }
        }
        __syncthreads();
    }

    float inv0 = 1.f / l0, inv1 = 1.f / l1;
#pragma unroll
    for (int dt = 0; dt < 8; dt++) {
        int cols = h * DH + dt * 8 + (lane & 3) * 2;
        __nv_bfloat162 p0 = __floats2bfloat162_rn(o[dt][0] * inv0, o[dt][1] * inv0);
        __nv_bfloat162 p1 = __floats2bfloat162_rn(o[dt][2] * inv1, o[dt][3] * inv1);
        *(__nv_bfloat162*)(g_attnb + (size_t)(b * SS + r0g) * DD + cols) = p0;
        *(__nv_bfloat162*)(g_attnb + (size_t)(b * SS + r0g + 8) * DD + cols) = p1;
    }
}

// ---------------- streaming fp32 -> bf16 cast (all weights in one launch) ----------------
#define N4_QKV (NLAYER*DD*3*DD/4)
#define N4_WO  (NLAYER*DD*DD/4)
#define N4_W1  (NLAYER*DD*FFD/4)
#define N4_W2  (NLAYER*FFD*DD/4)
__global__ void wcast_all(const float* __restrict__ Wqkv, const float* __restrict__ Wo,
                          const float* __restrict__ W1, const float* __restrict__ W2) {
    const int total = N4_QKV + N4_WO + N4_W1 + N4_W2;
    int stride = gridDim.x * blockDim.x;
    for (int i = blockIdx.x * blockDim.x + threadIdx.x; i < total; i += stride) {
        const float4* src;
        uint2* dst;
        int j = i;
        if (j < N4_QKV) { src = (const float4*)Wqkv; dst = (uint2*)g_Wqkv; }
        else if ((j -= N4_QKV) < N4_WO) { src = (const float4*)Wo; dst = (uint2*)g_Wo; }
        else if ((j -= N4_WO) < N4_W1) { src = (const float4*)W1; dst = (uint2*)g_W1; }
        else { j -= N4_W1; src = (const float4*)W2; dst = (uint2*)g_W2; }
        float4 v = src[j];
        __nv_bfloat162 p0 = __floats2bfloat162_rn(v.x, v.y);
        __nv_bfloat162 p1 = __floats2bfloat162_rn(v.z, v.w);
        dst[j] = make_uint2(*(uint32_t*)&p0, *(uint32_t*)&p1);
    }
}
__global__ void projcast(const float* __restrict__ W, __nv_bfloat16* __restrict__ o) {
    int k = blockIdx.x;
    for (int n = threadIdx.x; n < NPAD; n += blockDim.x)
        o[(size_t)k * NPAD + n] = (n < CVOC) ? __float2bfloat16(W[(size_t)k * CVOC + n]) : __nv_bfloat16(0.f);
}

// ---------------- embedding + sinusoidal PE (bf16 residual) ----------------
__global__ void embed_kernel(const int* __restrict__ tokens, const int* __restrict__ codes,
                             const float* __restrict__ tok_emb, const float* __restrict__ audio_emb) {
    int row = blockIdx.x;
    int b = row / SS, s = row % SS;
    const float* src; int pos;
    if (s < XL) { src = tok_emb + (size_t)tokens[b*XL + s] * DD; pos = s; }
    else {
        int sy = s - XL;
        int id = (sy == 0) ? BOS_ID : codes[b*CL + sy - 1];
        src = audio_emb + (size_t)id * DD; pos = sy;
    }
    __nv_bfloat16* dstb = g_hb + (size_t)row * DD;
    const float kinv = 9.210340371976184f / (float)DD;
    for (int d = threadIdx.x; d < DD; d += blockDim.x) {
        float freq = expf(-(float)(d & ~1) * kinv);
        float ang = (float)pos * freq;
        float pe = (d & 1) ? cosf(ang) : sinf(ang);
        dstb[d] = __float2bfloat16(src[d] + pe);
    }
}

// ---------------- hb = LN(hb + p0 + p1 + bias) (all bf16 I/O, fp32 math) ----------------
__global__ void __launch_bounds__(256) add_ln3(const __nv_bfloat16* __restrict__ p0,
        const __nv_bfloat16* __restrict__ p1, const float* __restrict__ bias,
        const float* __restrict__ w, const float* __restrict__ bvec) {
    __shared__ float red[8], red2[8];
    int row = blockIdx.x, tid = threadIdx.x, lane = tid & 31, wid = tid >> 5;

    uint2 hb2 = ((const uint2*)(g_hb + (size_t)row * DD))[tid];
    uint2 qa = ((const uint2*)(p0 + (size_t)row * DD))[tid];
    uint2 qb = ((const uint2*)(p1 + (size_t)row * DD))[tid];
    float4 bs = ((const float4*)bias)[tid];
    __nv_bfloat162 h0b = *(__nv_bfloat162*)&hb2.x, h1b = *(__nv_bfloat162*)&hb2.y;
    __nv_bfloat162 a0 = *(__nv_bfloat162*)&qa.x, a1 = *(__nv_bfloat162*)&qa.y;
    __nv_bfloat162 b0 = *(__nv_bfloat162*)&qb.x, b1 = *(__nv_bfloat162*)&qb.y;
    float4 v;
    v.x = __bfloat162float(h0b.x) + __bfloat162float(a0.x) + __bfloat162float(b0.x) + bs.x;
    v.y = __bfloat162float(h0b.y) + __bfloat162float(a0.y) + __bfloat162float(b0.y) + bs.y;
    v.z = __bfloat162float(h1b.x) + __bfloat162float(a1.x) + __bfloat162float(b1.x) + bs.z;
    v.w = __bfloat162float(h1b.y) + __bfloat162float(a1.y) + __bfloat162float(b1.y) + bs.w;

    float s = v.x + v.y + v.z + v.w;
#pragma unroll
    for (int o = 16; o; o >>= 1) s += __shfl_xor_sync(0xffffffff, s, o);
    if (lane == 0) red[wid] = s;
    __syncthreads();
    float tot = 0.f;
#pragma unroll
    for (int i = 0; i < 8; i++) tot += red[i];
    float mu = tot * (1.f / DD);

    float dx = v.x - mu, dy = v.y - mu, dz = v.z - mu, dw = v.w - mu;
    float s2 = dx * dx + dy * dy + dz * dz + dw * dw;
#pragma unroll
    for (int o = 16; o; o >>= 1) s2 += __shfl_xor_sync(0xffffffff, s2, o);
    if (lane == 0) red2[wid] = s2;
    __syncthreads();
    float tot2 = 0.f;
#pragma unroll
    for (int i = 0; i < 8; i++) tot2 += red2[i];
    float rstd = rsqrtf(tot2 * (1.f / DD) + 1e-5f);

    float4 w4 = ((const float4*)w)[tid];
    float4 b4 = ((const float4*)bvec)[tid];
    __nv_bfloat162 o0 = __floats2bfloat162_rn(dx * rstd * w4.x + b4.x, dy * rstd * w4.y + b4.y);
    __nv_bfloat162 o1 = __floats2bfloat162_rn(dz * rstd * w4.z + b4.z, dw * rstd * w4.w + b4.w);
    ((uint2*)(g_hb + (size_t)row * DD))[tid] = make_uint2(*(uint32_t*)&o0, *(uint32_t*)&o1);
}

// ---------------- final LN on audio rows only -> bf16 gather ----------------
__global__ void __launch_bounds__(256) lnf_gather(const float* __restrict__ w,
                                                  const float* __restrict__ bvec) {
    __shared__ float red[8], red2[8];
    int m = blockIdx.x, tid = threadIdx.x, lane = tid & 31, wid = tid >> 5;
    int b = m / YL, t = m % YL;

    uint2 hb2 = ((const uint2*)(g_hb + (size_t)(b * SS + XL + t) * DD))[tid];
    __nv_bfloat162 h0b = *(__nv_bfloat162*)&hb2.x, h1b = *(__nv_bfloat162*)&hb2.y;
    float4 v;
    v.x = __bfloat162float(h0b.x); v.y = __bfloat162float(h0b.y);
    v.z = __bfloat162float(h1b.x); v.w = __bfloat162float(h1b.y);

    float s = v.x + v.y + v.z + v.w;
#pragma unroll
    for (int o = 16; o; o >>= 1) s += __shfl_xor_sync(0xffffffff, s, o);
    if (lane == 0) red[wid] = s;
    __syncthreads();
    float tot = 0.f;
#pragma unroll
    for (int i = 0; i < 8; i++) tot += red[i];
    float mu = tot * (1.f / DD);

    float dx = v.x - mu, dy = v.y - mu, dz = v.z - mu, dw = v.w - mu;
    float s2 = dx * dx + dy * dy + dz * dz + dw * dw;
#pragma unroll
    for (int o = 16; o; o >>= 1) s2 += __shfl_xor_sync(0xffffffff, s2, o);
    if (lane == 0) red2[wid] = s2;
    __syncthreads();
    float tot2 = 0.f;
#pragma unroll
    for (int i = 0; i < 8; i++) tot2 += red2[i];
    float rstd = rsqrtf(tot2 * (1.f / DD) + 1e-5f);

    float4 w4 = ((const float4*)w)[tid];
    float4 b4 = ((const float4*)bvec)[tid];
    __nv_bfloat162 h0 = __floats2bfloat162_rn(dx * rstd * w4.x + b4.x, dy * rstd * w4.y + b4.y);
    __nv_bfloat162 h1 = __floats2bfloat162_rn(dz * rstd * w4.z + b4.z, dw * rstd * w4.w + b4.w);
    ((uint2*)(g_xb + (size_t)m * DD))[tid] = make_uint2(*(uint32_t*)&h0, *(uint32_t*)&h1);
}

// ---------------- per-row NLL (sums two fp32 split-K logit partials) ----------------
__device__ __forceinline__ float blk_reduce_max(float v, float* red) {
    int t = threadIdx.x;
    red[t] = v; __syncthreads();
    for (int s = 128; s > 0; s >>= 1) { if (t < s) red[t] = fmaxf(red[t], red[t + s]); __syncthreads(); }
    float r = red[0]; __syncthreads();
    return r;
}
__device__ __forceinline__ float blk_reduce_sum(float v, float* red) {
    int t = threadIdx.x;
    red[t] = v; __syncthreads();
    for (int s = 128; s > 0; s >>= 1) { if (t < s) red[t] += red[t + s]; __syncthreads(); }
    float r = red[0]; __syncthreads();
    return r;
}
__global__ void nll_kernel(const int* __restrict__ codes) {
    __shared__ float red[256];
    __shared__ float rowbuf[CVOC];
    int m = blockIdx.x;
    int b = m / YL, t = m % YL;
    const float* r0 = g_logits + (size_t)m * NPAD;
    const float* r1 = g_logits + (size_t)PROWS * NPAD + (size_t)m * NPAD;
    int tid = threadIdx.x;

    float lmax = -1e30f;
    for (int j = tid; j < CVOC; j += 256) {
        float v = r0[j] + r1[j];
        rowbuf[j] = v;
        lmax = fmaxf(lmax, v);
    }
    lmax = blk_reduce_max(lmax, red);
    float lsum = 0.f;
    for (int j = tid; j < CVOC; j += 256) lsum += expf(rowbuf[j] - lmax);
    lsum = blk_reduce_sum(lsum, red);
    if (tid == 0) {
        int tgt = (t < CL) ? codes[b * CL + t] : EOS_ID;
        g_nll[m] = lmax + logf(lsum) - rowbuf[tgt];
    }
}

__global__ void mean_kernel(float* __restrict__ out) {
    __shared__ float red[256];
    int tid = threadIdx.x;
    float s = 0.f;
    for (int i = tid; i < PROWS; i += 256) s += g_nll[i];
    s = blk_reduce_sum(s, red);
    if (tid == 0) out[0] = s / (float)PROWS;
}

// ---------------- launch ----------------
extern "C" void kernel_launch(void* const* d_in, const int* in_sizes, int n_in,
                              void* d_out, int out_size) {
    const int*   tokens    = (const int*)d_in[0];
    const int*   codes     = (const int*)d_in[1];
    const float* tok_emb   = (const float*)d_in[2];
    const float* audio_emb = (const float*)d_in[3];
    const float* Wqkv      = (const float*)d_in[4];
    const float* b_qkv     = (const float*)d_in[5];
    const float* Wo        = (const float*)d_in[6];
    const float* b_o       = (const float*)d_in[7];
    const float* W1        = (const float*)d_in[8];
    const float* b1        = (const float*)d_in[9];
    const float* W2        = (const float*)d_in[10];
    const float* b2        = (const float*)d_in[11];
    const float* ln1_w     = (const float*)d_in[12];
    const float* ln1_b     = (const float*)d_in[13];
    const float* ln2_w     = (const float*)d_in[14];
    const float* ln2_b     = (const float*)d_in[15];
    const float* lnf_w     = (const float*)d_in[16];
    const float* lnf_b     = (const float*)d_in[17];
    const float* proj_w    = (const float*)d_in[18];

    float *logitsP;
    __nv_bfloat16 *hbP, *qkvbP, *attnbP, *tmpbP, *ffbP, *xbP, *WqkvP, *WoP, *W1P, *W2P, *projP;
    cudaGetSymbolAddress((void**)&hbP, g_hb);
    cudaGetSymbolAddress((void**)&qkvbP, g_qkvb);
    cudaGetSymbolAddress((void**)&attnbP, g_attnb);
    cudaGetSymbolAddress((void**)&tmpbP, g_tmpb);
    cudaGetSymbolAddress((void**)&ffbP, g_ffb);
    cudaGetSymbolAddress((void**)&xbP, g_xb);
    cudaGetSymbolAddress((void**)&logitsP, g_logits);
    cudaGetSymbolAddress((void**)&WqkvP, g_Wqkv);
    cudaGetSymbolAddress((void**)&WoP, g_Wo);
    cudaGetSymbolAddress((void**)&W1P, g_W1);
    cudaGetSymbolAddress((void**)&W2P, g_W2);
    cudaGetSymbolAddress((void**)&projP, g_proj);

    cudaFuncSetAttribute(gemm_mma<1,0,1,1>, cudaFuncAttributeMaxDynamicSharedMemorySize, GEMM_SMEM);
    cudaFuncSetAttribute(gemm_mma<1,1,1,1>, cudaFuncAttributeMaxDynamicSharedMemorySize, GEMM_SMEM);
    cudaFuncSetAttribute(gemm_mma<1,0,0,2>, cudaFuncAttributeMaxDynamicSharedMemorySize, GEMM_SMEM);
    cudaFuncSetAttribute(gemm_mma<0,0,0,2>, cudaFuncAttributeMaxDynamicSharedMemorySize, GEMM_SMEM);
    cudaFuncSetAttribute(flash_attn, cudaFuncAttributeMaxDynamicSharedMemorySize, FLASH_SMEM);

    wcast_all<<<2048, 256>>>(Wqkv, Wo, W1, W2);
    projcast<<<DD, 256>>>(proj_w, projP);

    embed_kernel<<<MROWS, 256>>>(tokens, codes, tok_emb, audio_emb);

    for (int l = 0; l < NLAYER; l++) {
        gemm_mma<1,0,1,1><<<dim3(3*DD/128, MROWS/128, 1), 256, GEMM_SMEM>>>(
            qkvbP, hbP, WqkvP + (size_t)l*DD*3*DD, b_qkv + (size_t)l*3*DD, MROWS, DD, 3*DD);
        flash_attn<<<dim3(SS/128, BB*NH), 256, FLASH_SMEM>>>(qkvbP);
        gemm_mma<1,0,0,2><<<dim3(DD/128, MROWS/128, 2), 256, GEMM_SMEM>>>(
            tmpbP, attnbP, WoP + (size_t)l*DD*DD, nullptr, MROWS, DD, DD);
        add_ln3<<<MROWS, 256>>>(tmpbP, tmpbP + (size_t)MROWS*DD, b_o + (size_t)l*DD,
                                ln1_w + l*DD, ln1_b + l*DD);
        gemm_mma<1,1,1,1><<<dim3(FFD/128, MROWS/128, 1), 256, GEMM_SMEM>>>(
            ffbP, hbP, W1P + (size_t)l*DD*FFD, b1 + (size_t)l*FFD, MROWS, DD, FFD);
        gemm_mma<1,0,0,2><<<dim3(DD/128, MROWS/128, 2), 256, GEMM_SMEM>>>(
            tmpbP, ffbP, W2P + (size_t)l*FFD*DD, nullptr, MROWS, FFD, DD);
        add_ln3<<<MROWS, 256>>>(tmpbP, tmpbP + (size_t)MROWS*DD, b2 + (size_t)l*DD,
                                ln2_w + l*DD, ln2_b + l*DD);
    }

    lnf_gather<<<PROWS, 256>>>(lnf_w, lnf_b);
    gemm_mma<0,0,0,2><<<dim3(NPAD/128, PROWS/128, 2), 256, GEMM_SMEM>>>(
        logitsP, xbP, projP, nullptr, PROWS, DD, NPAD);
    nll_kernel<<<PROWS, 256>>>(codes);
    mean_kernel<<<1, 256>>>((float*)d_out);
}